// round 4
// baseline (speedup 1.0000x reference)
#include <cuda_runtime.h>

#define Bb   8
#define Nn   2048
#define Dd   128
#define Fin  10
#define ALPHA 0.02f
#define TI   32
#define CJ   128
#define NCHUNK (Nn / CJ)

typedef unsigned long long ull;

// ---------------- device scratch ----------------
__device__ float g_X [Bb * Nn * Dd];      // 8 MB (post fc1+LN+lrelu)
__device__ float g_Wh[Bb * Nn * Dd];      // 8 MB
__device__ float g_e1[Bb * Nn];
__device__ float g_e2[Bb * Nn];
__device__ float g_e2max[Bb];
__device__ float g_pooled[Bb * Dd];

// ---------------- helpers ----------------
__device__ __forceinline__ float warpSum(float v) {
#pragma unroll
    for (int o = 16; o > 0; o >>= 1) v += __shfl_xor_sync(0xffffffffu, v, o);
    return v;
}
__device__ __forceinline__ float warpMax(float v) {
#pragma unroll
    for (int o = 16; o > 0; o >>= 1) v = fmaxf(v, __shfl_xor_sync(0xffffffffu, v, o));
    return v;
}
__device__ __forceinline__ float lrelu(float x) { return x >= 0.f ? x : ALPHA * x; }

__device__ __forceinline__ void atomicMaxFloat(float* addr, float v) {
    if (v >= 0.f) atomicMax((int*)addr, __float_as_int(v));
    else          atomicMin((unsigned int*)addr, __float_as_uint(v));
}
__device__ __forceinline__ void ffma2(ull& a, ull b, ull c) {
    asm("fma.rn.f32x2 %0, %1, %2, %0;" : "+l"(a) : "l"(b), "l"(c));
}
__device__ __forceinline__ ull packf2(float v) {
    ull r; asm("mov.b64 %0, {%1, %1};" : "=l"(r) : "f"(v)); return r;
}

// ---------------- K0: init pooled ----------------
__global__ void k_init() {
    g_pooled[threadIdx.x] = -3.402823466e38f;
}

// ---------------- K1a: fc1 + LN + lrelu -> g_X ----------------
// one block (128 threads) per node; W1 staged in smem (coalesced)
__global__ __launch_bounds__(128) void k1a(
    const float* __restrict__ h, const float* __restrict__ W1, const float* __restrict__ b1)
{
    __shared__ float w1s[Dd * Fin];
    __shared__ float hsh[Fin];
    __shared__ float rs1[4], rs2[4];

    const int node = blockIdx.x;
    const int t = threadIdx.x;
    const int lane = t & 31, wrp = t >> 5;

#pragma unroll
    for (int idx = t; idx < Dd * Fin; idx += 128) w1s[idx] = W1[idx];
    if (t < Fin) hsh[t] = h[node * Fin + t];
    __syncthreads();

    float x = b1[t];
#pragma unroll
    for (int f = 0; f < Fin; ++f) x += hsh[f] * w1s[t * Fin + f];

    float s1 = warpSum(x);
    float s2 = warpSum(x * x);
    if (lane == 0) { rs1[wrp] = s1; rs2[wrp] = s2; }
    __syncthreads();
    float S1 = rs1[0] + rs1[1] + rs1[2] + rs1[3];
    float S2 = rs2[0] + rs2[1] + rs2[2] + rs2[3];
    float mean = S1 * (1.f / Dd);
    float var  = S2 * (1.f / Dd) - mean * mean;
    float xn = (x - mean) * rsqrtf(var + 1e-5f);
    g_X[(size_t)node * Dd + t] = lrelu(xn);
}

// ---------------- K1b: Wh = X @ Wg^T + bg, plus e1/e2 ----------------
// 128 blocks x 512 threads; per block: 128 nodes. Wg transposed in smem (pad 132).
__global__ __launch_bounds__(512) void k1b(
    const float* __restrict__ Wg, const float* __restrict__ bg,
    const float* __restrict__ a1, const float* __restrict__ a2)
{
    extern __shared__ float sm[];
    float* wgt = sm;                 // [128 k][132] (value at wgt[k*132+d] = Wg[d][k])
    float* xsh = sm + 128 * 132;     // [128 n][128 k]

    const int t = threadIdx.x;
    const int lane = t & 31, wrp = t >> 5;    // wrp 0..15
    const int n0 = blockIdx.x * 128;

    // load Wg transposed
#pragma unroll
    for (int it = 0; it < 32; ++it) {
        int idx = it * 512 + t;
        int d = idx >> 7, k = idx & 127;
        wgt[k * 132 + d] = Wg[idx];
    }
    // load X tile
    {
        const float4* xs = (const float4*)(g_X) + (size_t)n0 * 32;
        float4* xd = (float4*)xsh;
#pragma unroll
        for (int it = 0; it < 8; ++it) xd[it * 512 + t] = xs[it * 512 + t];
    }
    __syncthreads();

    // GEMM: warp wrp -> nodes n0 + wrp*8 .. +8; lane -> dims 4*lane..4*lane+3
    ull acc[8][2];
#pragma unroll
    for (int n = 0; n < 8; ++n) { acc[n][0] = 0ull; acc[n][1] = 0ull; }

    for (int k = 0; k < 128; ++k) {
        ulonglong2 wv = *(const ulonglong2*)&wgt[k * 132 + lane * 4];
#pragma unroll
        for (int n = 0; n < 8; ++n) {
            float xv = xsh[(wrp * 8 + n) * 128 + k];
            ull xx = packf2(xv);
            ffma2(acc[n][0], xx, wv.x);
            ffma2(acc[n][1], xx, wv.y);
        }
    }

    const float4 bgv = ((const float4*)bg)[lane];
    const float4 a1v = ((const float4*)a1)[lane];
    const float4 a2v = ((const float4*)a2)[lane];

#pragma unroll
    for (int n = 0; n < 8; ++n) {
        const int node = n0 + wrp * 8 + n;
        float2 lo = *(float2*)&acc[n][0];
        float2 hi = *(float2*)&acc[n][1];
        float4 wh;
        wh.x = lo.x + bgv.x; wh.y = lo.y + bgv.y;
        wh.z = hi.x + bgv.z; wh.w = hi.y + bgv.w;
        ((float4*)g_Wh)[(size_t)node * 32 + lane] = wh;
        float p1 = wh.x * a1v.x + wh.y * a1v.y + wh.z * a1v.z + wh.w * a1v.w;
        float p2 = wh.x * a2v.x + wh.y * a2v.y + wh.z * a2v.z + wh.w * a2v.w;
        p1 = warpSum(p1);
        p2 = warpSum(p2);
        if (lane == 0) { g_e1[node] = p1; g_e2[node] = p2; }
    }
}

// ---------------- K1c: per-batch max of e2 ----------------
__global__ void k_e2max() {
    const int b = blockIdx.x, t = threadIdx.x;
    const int lane = t & 31, wrp = t >> 5;
    __shared__ float sm[4];
    float mx = -3.402823466e38f;
    for (int k = t; k < Nn; k += 128) mx = fmaxf(mx, g_e2[b * Nn + k]);
    mx = warpMax(mx);
    if (lane == 0) sm[wrp] = mx;
    __syncthreads();
    if (t == 0) g_e2max[b] = fmaxf(fmaxf(sm[0], sm[1]), fmaxf(sm[2], sm[3]));
}

// ---------------- K2: masked attention + weighted sum + LN + maxpool ----------------
// grid = B*(N/TI) = 512 blocks, 128 threads. Lane owns 4 dims (float4 acc as 2xf32x2),
// warps split j into quarters per chunk. w stored scalar in smem, read LDS.32 broadcast.
// Softmax max uses analytic bound m_i = lrelu(e1_i + max_j e2_j) -> one streaming pass.
__global__ __launch_bounds__(128, 2) void k2_attn(const int* __restrict__ adj)
{
    extern __shared__ char smraw[];
    float* wh_sh = (float*)smraw;                    // [CJ j][Dd d]   64 KB
    float* w_sh  = (float*)(smraw + CJ * Dd * 4);    // [TI i][CJ j]   16 KB

    __shared__ float e1_sh[TI], m_sh[TI], l_sh[TI];
    __shared__ float lsum[TI][4];
    __shared__ float rs1[4], rs2[4];

    const int bid = blockIdx.x;
    const int b   = bid >> 6;              // 64 blocks per batch
    const int i0  = (bid & 63) * TI;
    const int t   = threadIdx.x;
    const int lane = t & 31, wrp = t >> 5;

    if (t < TI) {
        float e1v = g_e1[(b << 11) + i0 + t];
        e1_sh[t] = e1v;
        m_sh[t]  = lrelu(e1v + g_e2max[b]);
        lsum[t][0] = lsum[t][1] = lsum[t][2] = lsum[t][3] = 0.f;
    }

    ull acc[2 * TI];
#pragma unroll
    for (int i = 0; i < 2 * TI; ++i) acc[i] = 0ull;

    __syncthreads();

    for (int c = 0; c < NCHUNK; ++c) {
        const int jb = c * CJ;

        // stage Wh chunk [CJ x Dd]
        {
            const float4* src = (const float4*)(g_Wh + ((size_t)((b << 11) + jb) << 7));
            float4* dst = (float4*)wh_sh;
#pragma unroll
            for (int it = 0; it < 32; ++it) dst[it * 128 + t] = src[it * 128 + t];
        }

        // scores: thread t <-> column j = jb + t ; scalar w to smem; l reduced now
        {
            const float e2v = g_e2[(b << 11) + jb + t];
            const int* adjp = adj + ((size_t)((b << 11) + i0)) * Nn + jb + t;
#pragma unroll
            for (int hb = 0; hb < TI; hb += 16) {
                int av[16];
#pragma unroll
                for (int k = 0; k < 16; ++k) av[k] = adjp[(size_t)(hb + k) * Nn];
                float w[16];
#pragma unroll
                for (int k = 0; k < 16; ++k) {
                    const int i = hb + k;
                    float s = lrelu(e1_sh[i] + e2v);
                    w[k] = (av[k] != 0) ? __expf(s - m_sh[i]) : 0.f;
                    w_sh[i * CJ + t] = w[k];
                }
#pragma unroll
                for (int k = 0; k < 16; ++k) {
                    float v = warpSum(w[k]);
                    if (lane == 0) lsum[hb + k][wrp] += v;
                }
            }
        }
        __syncthreads();

        // FMA: warp handles j-quarter [wrp*32, wrp*32+32)
        {
            const ulonglong2* whq = (const ulonglong2*)wh_sh;   // [j][32 lane-chunks]
            const float* wrow = w_sh + (wrp << 5);
            ulonglong2 whn = whq[(wrp << 5) * 32 + lane];
#pragma unroll 1
            for (int jj = 0; jj < 32; ++jj) {
                ulonglong2 wh2 = whn;
                int jn = (wrp << 5) + ((jj + 1) & 31);
                whn = whq[jn * 32 + lane];
#pragma unroll
                for (int i = 0; i < TI; ++i) {
                    ull ww = packf2(wrow[i * CJ + jj]);
                    ffma2(acc[2 * i],     ww, wh2.x);
                    ffma2(acc[2 * i + 1], ww, wh2.y);
                }
            }
        }
        __syncthreads();
    }

    if (t < TI) l_sh[t] = lsum[t][0] + lsum[t][1] + lsum[t][2] + lsum[t][3];

    // cross-warp reduce of acc partials via smem (reuse wh_sh: 4 warps x 32 i x 128 d)
    {
        ulonglong2* redq = (ulonglong2*)wh_sh;
#pragma unroll
        for (int i = 0; i < TI; ++i)
            redq[(wrp * TI + i) * 32 + lane] = make_ulonglong2(acc[2 * i], acc[2 * i + 1]);
    }
    __syncthreads();

    // per-row: sum partials, divide by l, LN, lrelu, maxpool
    for (int i = 0; i < TI; ++i) {
        float v = wh_sh[(0 * TI + i) * Dd + t] + wh_sh[(1 * TI + i) * Dd + t]
                + wh_sh[(2 * TI + i) * Dd + t] + wh_sh[(3 * TI + i) * Dd + t];
        v *= 1.f / l_sh[i];
        float s1 = warpSum(v);
        float s2 = warpSum(v * v);
        if (lane == 0) { rs1[wrp] = s1; rs2[wrp] = s2; }
        __syncthreads();
        float S1 = rs1[0] + rs1[1] + rs1[2] + rs1[3];
        float S2 = rs2[0] + rs2[1] + rs2[2] + rs2[3];
        __syncthreads();
        float mean = S1 * (1.f / Dd);
        float var  = S2 * (1.f / Dd) - mean * mean;
        float nv = lrelu((v - mean) * rsqrtf(var + 1e-5f));
        atomicMaxFloat(&g_pooled[(b << 7) + t], nv);
    }
}

// ---------------- K3: head + log_softmax ----------------
__global__ void k3_out(const float* __restrict__ W2, const float* __restrict__ b2,
                       float* __restrict__ out)
{
    const int t = threadIdx.x;          // 256
    const int b = t >> 5, lane = t & 31;
    if (b < Bb) {
        float p0 = 0.f, p1 = 0.f;
        for (int d = lane; d < Dd; d += 32) {
            float pv = g_pooled[b * Dd + d];
            p0 += pv * W2[d];
            p1 += pv * W2[Dd + d];
        }
        p0 = warpSum(p0);
        p1 = warpSum(p1);
        if (lane == 0) {
            float o0 = p0 + b2[0], o1 = p1 + b2[1];
            float m = fmaxf(o0, o1);
            float lse = m + logf(expf(o0 - m) + expf(o1 - m));
            out[b * 2 + 0] = o0 - lse;
            out[b * 2 + 1] = o1 - lse;
        }
    }
}

// ---------------- launch ----------------
extern "C" void kernel_launch(void* const* d_in, const int* in_sizes, int n_in,
                              void* d_out, int out_size)
{
    const float* h   = (const float*)d_in[0];
    const int*   adj = (const int*)  d_in[1];
    const float* W1  = (const float*)d_in[2];
    const float* b1  = (const float*)d_in[3];
    const float* Wg  = (const float*)d_in[4];
    const float* bg  = (const float*)d_in[5];
    const float* a1  = (const float*)d_in[6];
    const float* a2  = (const float*)d_in[7];
    const float* W2  = (const float*)d_in[8];
    const float* b2  = (const float*)d_in[9];
    float* out = (float*)d_out;

    const int smem_k1b = (128 * 132 + 128 * 128) * 4;          // 133120
    const int smem_k2  = CJ * Dd * 4 + TI * CJ * 4;            // 81920
    cudaFuncSetAttribute(k1b, cudaFuncAttributeMaxDynamicSharedMemorySize, smem_k1b);
    cudaFuncSetAttribute(k2_attn, cudaFuncAttributeMaxDynamicSharedMemorySize, smem_k2);

    k_init<<<1, Bb * Dd>>>();
    k1a<<<Bb * Nn, 128>>>(h, W1, b1);
    k1b<<<Bb * Nn / 128, 512, smem_k1b>>>(Wg, bg, a1, a2);
    k_e2max<<<Bb, 128>>>();
    k2_attn<<<Bb * (Nn / TI), 128, smem_k2>>>(adj);
    k3_out<<<1, 256>>>(W2, b2, out);
}

// round 7
// speedup vs baseline: 2.7570x; 2.7570x over previous
#include <cuda_runtime.h>
#include <cuda_fp16.h>
#include <cstdint>

#define Bb 8
#define Nn 2048
#define Dd 128
#define Fin 10
#define ALPHA 0.02f
typedef unsigned long long ull;

// ---------------- device scratch ----------------
__device__ __align__(16) __half g_Whh[Bb * Nn * Dd];   // 4MB hi
__device__ __align__(16) __half g_Whl[Bb * Nn * Dd];   // 4MB lo
__device__ float g_e1[Bb * Nn];
__device__ float g_e2[Bb * Nn];
__device__ float g_P[Bb * Nn];
__device__ float g_R[Bb * Nn];
__device__ __align__(16) float4 g_QS[Bb * Nn];         // (e2, Q, S, 0)
__device__ float g_e2max[Bb];
__device__ float g_pooled[Bb * Dd];

// ---------------- helpers ----------------
__device__ __forceinline__ float warpSum(float v) {
#pragma unroll
    for (int o = 16; o > 0; o >>= 1) v += __shfl_xor_sync(0xffffffffu, v, o);
    return v;
}
__device__ __forceinline__ float lrelu(float x) { return fmaxf(x, ALPHA * x); }
__device__ __forceinline__ void atomicMaxFloat(float* a, float v) {
    if (v >= 0.f) atomicMax((int*)a, __float_as_int(v));
    else          atomicMin((unsigned int*)a, __float_as_uint(v));
}
__device__ __forceinline__ void ffma2(ull& a, ull b, ull c) {
    asm("fma.rn.f32x2 %0, %1, %2, %0;" : "+l"(a) : "l"(b), "l"(c));
}
__device__ __forceinline__ ull packf2(float v) {
    ull r; asm("mov.b64 %0, {%1, %1};" : "=l"(r) : "f"(v)); return r;
}
__device__ __forceinline__ uint32_t smem_u32(const void* p) {
    uint32_t a;
    asm("{ .reg .u64 t; cvta.to.shared.u64 t, %1; cvt.u32.u64 %0, t; }" : "=r"(a) : "l"(p));
    return a;
}
__device__ __forceinline__ void ldsm4(uint32_t* r, uint32_t a) {
    asm volatile("ldmatrix.sync.aligned.m8n8.x4.shared.b16 {%0,%1,%2,%3}, [%4];"
        : "=r"(r[0]), "=r"(r[1]), "=r"(r[2]), "=r"(r[3]) : "r"(a));
}
__device__ __forceinline__ void ldsm4t(uint32_t* r, uint32_t a) {
    asm volatile("ldmatrix.sync.aligned.m8n8.x4.trans.shared.b16 {%0,%1,%2,%3}, [%4];"
        : "=r"(r[0]), "=r"(r[1]), "=r"(r[2]), "=r"(r[3]) : "r"(a));
}
__device__ __forceinline__ void mma16816(float* d, const uint32_t* a, uint32_t b0, uint32_t b1) {
    asm volatile("mma.sync.aligned.m16n8k16.row.col.f32.f16.f16.f32 "
        "{%0,%1,%2,%3},{%4,%5,%6,%7},{%8,%9},{%0,%1,%2,%3};"
        : "+f"(d[0]), "+f"(d[1]), "+f"(d[2]), "+f"(d[3])
        : "r"(a[0]), "r"(a[1]), "r"(a[2]), "r"(a[3]), "r"(b0), "r"(b1));
}
__device__ __forceinline__ void cpa16(uint32_t dst, const void* src) {
    asm volatile("cp.async.cg.shared.global [%0], [%1], 16;" :: "r"(dst), "l"(src));
}
__device__ __forceinline__ void cpa_commit() { asm volatile("cp.async.commit_group;"); }

// ---------------- K0 ----------------
__global__ void k_init() {
    g_pooled[threadIdx.x] = -3.402823466e38f;
    if (threadIdx.x < Bb) g_e2max[threadIdx.x] = -3.402823466e38f;
}

// ---------------- K1: fc1+LN+lrelu -> Wg GEMM -> e1/e2/e2max -> Wh fp16 hi/lo ---------
// 128 blocks x 512 threads; block = 128 nodes
__global__ __launch_bounds__(512, 1) void k1(
    const float* __restrict__ h, const float* __restrict__ W1, const float* __restrict__ b1,
    const float* __restrict__ Wg, const float* __restrict__ bg,
    const float* __restrict__ a1, const float* __restrict__ a2)
{
    extern __shared__ __align__(16) float sm[];
    float* wgt = sm;                 // [128 k][132]
    float* xsh = sm + 16896;         // [128 n][129]
    float* hsh = sm + 33408;         // [128 n][10]
    float* w1s = sm + 34688;         // [128 d][10]
    float* b1s = sm + 35968;         // [128]
    float* red = sm + 36096;         // [2][4][128]

    const int t = threadIdx.x, lane = t & 31, wrp = t >> 5;
    const int n0 = blockIdx.x * 128;
    const int b  = blockIdx.x >> 4;

#pragma unroll
    for (int it = 0; it < 32; ++it) {
        int idx = it * 512 + t;
        wgt[(idx & 127) * 132 + (idx >> 7)] = Wg[idx];
    }
#pragma unroll
    for (int idx = t; idx < 128 * Fin; idx += 512) {
        hsh[idx] = h[n0 * Fin + idx];
        w1s[idx] = W1[idx];
    }
    if (t < 128) b1s[t] = b1[t];
    __syncthreads();

    // fc1 + LN + lrelu: thread -> (node n = t&127, dim-quarter qq = t>>7)
    {
        const int n = t & 127, qq = t >> 7;
        float hv[Fin];
#pragma unroll
        for (int f = 0; f < Fin; ++f) hv[f] = hsh[n * Fin + f];
        float xr[32], s1 = 0.f, s2 = 0.f;
#pragma unroll
        for (int k = 0; k < 32; ++k) {
            const int d = qq * 32 + k;
            float x = b1s[d];
#pragma unroll
            for (int f = 0; f < Fin; ++f) x += hv[f] * w1s[d * Fin + f];
            xr[k] = x; s1 += x; s2 += x * x;
        }
        red[qq * 128 + n] = s1;
        red[512 + qq * 128 + n] = s2;
        __syncthreads();
        float S1 = red[n] + red[128 + n] + red[256 + n] + red[384 + n];
        float S2 = red[512 + n] + red[640 + n] + red[768 + n] + red[896 + n];
        float mean = S1 * (1.f / Dd);
        float var  = S2 * (1.f / Dd) - mean * mean;
        float rstd = rsqrtf(var + 1e-5f);
#pragma unroll
        for (int k = 0; k < 32; ++k)
            xsh[n * 129 + qq * 32 + k] = lrelu((xr[k] - mean) * rstd);
    }
    __syncthreads();

    // GEMM: warp -> 8 nodes, lane -> dims 4*lane..+3
    ull acc[8][2];
#pragma unroll
    for (int n = 0; n < 8; ++n) { acc[n][0] = 0ull; acc[n][1] = 0ull; }
    for (int k = 0; k < 128; ++k) {
        ulonglong2 wv = *(const ulonglong2*)&wgt[k * 132 + lane * 4];
#pragma unroll
        for (int n = 0; n < 8; ++n) {
            ull xx = packf2(xsh[(wrp * 8 + n) * 129 + k]);
            ffma2(acc[n][0], xx, wv.x);
            ffma2(acc[n][1], xx, wv.y);
        }
    }

    const float4 bgv = ((const float4*)bg)[lane];
    const float4 a1v = ((const float4*)a1)[lane];
    const float4 a2v = ((const float4*)a2)[lane];
    float e2mx = -3.402823466e38f;
#pragma unroll
    for (int n = 0; n < 8; ++n) {
        const int node = n0 + wrp * 8 + n;
        float2 lo = *(float2*)&acc[n][0];
        float2 hi = *(float2*)&acc[n][1];
        float v0 = lo.x + bgv.x, v1 = lo.y + bgv.y;
        float v2 = hi.x + bgv.z, v3 = hi.y + bgv.w;

        // fp16 hi/lo split, store
        __half h0 = __float2half_rn(v0), h1 = __float2half_rn(v1);
        __half h2 = __float2half_rn(v2), h3 = __float2half_rn(v3);
        __half l0 = __float2half_rn(v0 - __half2float(h0));
        __half l1 = __float2half_rn(v1 - __half2float(h1));
        __half l2 = __float2half_rn(v2 - __half2float(h2));
        __half l3 = __float2half_rn(v3 - __half2float(h3));
        ((__half2*)g_Whh)[node * 64 + lane * 2]     = __halves2half2(h0, h1);
        ((__half2*)g_Whh)[node * 64 + lane * 2 + 1] = __halves2half2(h2, h3);
        ((__half2*)g_Whl)[node * 64 + lane * 2]     = __halves2half2(l0, l1);
        ((__half2*)g_Whl)[node * 64 + lane * 2 + 1] = __halves2half2(l2, l3);

        float p1 = warpSum(v0 * a1v.x + v1 * a1v.y + v2 * a1v.z + v3 * a1v.w);
        float p2 = warpSum(v0 * a2v.x + v1 * a2v.y + v2 * a2v.z + v3 * a2v.w);
        if (lane == 0) {
            g_e1[node] = p1;
            g_e2[node] = p2;
            e2mx = fmaxf(e2mx, p2);
        }
    }
    if (lane == 0) atomicMaxFloat(&g_e2max[b], e2mx);
}

// ---------------- K1c: factorized softmax terms ----------------
__global__ void k1c() {
    const int idx = blockIdx.x * 512 + threadIdx.x;     // 16384 nodes
    const int b = idx >> 11;
    float e1 = g_e1[idx], e2 = g_e2[idx], em = g_e2max[b];
    float m = lrelu(e1 + em);
    g_P[idx] = __expf(e1 + em - m);
    g_R[idx] = __expf(ALPHA * (e1 + em) - m);
    float Q = __expf(e2 - em);
    float S = __expf(ALPHA * (e2 - em));
    g_QS[idx] = make_float4(e2, Q, S, 0.f);
}

// ---------------- K2: masked attention via mma.sync ----------------
// 128 blocks x 256 threads (8 warps); block = (b, 128 i-rows); 32 chunks of 64 j.
// smem dyn layout (bytes): WhH[buf]= buf*34816, WhL = +17408 (64r x 136h);
//                          wH[buf] = 69632 + buf*36864, wL = +18432 (128r x 72h)
__global__ __launch_bounds__(256, 1) void k2_attn(const int* __restrict__ adj)
{
    extern __shared__ __align__(16) char smd[];
    __shared__ float e1s[128], Ps[128], Rs[128], lsh[128];
    __shared__ float pm[8][128];

    const int t = threadIdx.x, lane = t & 31, wrp = t >> 5;
    const int b  = blockIdx.x >> 4;
    const int i0 = (blockIdx.x & 15) << 7;
    const uint32_t base = smem_u32(smd);

    if (t < 128) {
        int idx = (b << 11) + i0 + t;
        e1s[t] = g_e1[idx];
        Ps[t]  = g_P[idx];
        Rs[t]  = g_R[idx];
    }
    __syncthreads();

    float acc[16][4];
#pragma unroll
    for (int i = 0; i < 16; ++i)
#pragma unroll
        for (int q = 0; q < 4; ++q) acc[i][q] = 0.f;
    float lsum[16];
#pragma unroll
    for (int r = 0; r < 16; ++r) lsum[r] = 0.f;

    // ---- stage Wh(chunk) into buf via cp.async ----
    auto stage_wh = [&](int cc, int bf) {
        const char* sH = (const char*)(g_Whh + ((size_t)((b << 11) + cc * 64) << 7));
        const char* sL = (const char*)(g_Whl + ((size_t)((b << 11) + cc * 64) << 7));
        uint32_t dH = base + bf * 34816;
        uint32_t dL = dH + 17408;
#pragma unroll
        for (int q = 0; q < 4; ++q) {
            int task = q * 256 + t;             // 0..1023
            int row = task >> 4, seg = task & 15;
            cpa16(dH + row * 272 + seg * 16, sH + row * 256 + seg * 16);
        }
#pragma unroll
        for (int q = 0; q < 4; ++q) {
            int task = q * 256 + t;
            int row = task >> 4, seg = task & 15;
            cpa16(dL + row * 272 + seg * 16, sL + row * 256 + seg * 16);
        }
    };

    // ---- score phase: warp -> rows wrp*16..+16; lane -> j = 2*lane, 2*lane+1 ----
    auto score = [&](int cc, int bf) {
        uint32_t wH = base + 69632 + bf * 36864;
        uint32_t wL = wH + 18432;
        const float4 qs0 = g_QS[(b << 11) + cc * 64 + 2 * lane];
        const float4 qs1 = g_QS[(b << 11) + cc * 64 + 2 * lane + 1];
        const int rbase = wrp * 16;
        const int2* ap = (const int2*)(adj + ((size_t)((b << 11) + i0 + rbase) << 11) + cc * 64) + lane;
#pragma unroll
        for (int rb = 0; rb < 16; rb += 4) {
            int2 av[4];
#pragma unroll
            for (int q = 0; q < 4; ++q) av[q] = ap[(size_t)(rb + q) << 10];
#pragma unroll
            for (int q = 0; q < 4; ++q) {
                const int r = rb + q;
                const int row = rbase + r;
                float e1r = e1s[row], Pr = Ps[row], Rr = Rs[row];
                float f0 = (e1r + qs0.x >= 0.f) ? Pr * qs0.y : Rr * qs0.z;
                float f1 = (e1r + qs1.x >= 0.f) ? Pr * qs1.y : Rr * qs1.z;
                float w0 = (av[q].x != 0) ? f0 : 0.f;
                float w1 = (av[q].y != 0) ? f1 : 0.f;
                lsum[r] += w0 + w1;
                __half2 hh = __floats2half2_rn(w0, w1);
                __half2 ll = __floats2half2_rn(w0 - __low2float(hh), w1 - __high2float(hh));
                *(__half2*)(smd + (wH - base) + row * 144 + lane * 4) = hh;
                *(__half2*)(smd + (wL - base) + row * 144 + lane * 4) = ll;
            }
        }
    };

    // ---- mma phase ----
    const uint32_t arow = wrp * 16 + ((lane >> 3) & 1) * 8 + (lane & 7);
    const uint32_t brow = ((lane >> 3) & 1) * 8 + (lane & 7);
    const uint32_t csel = (lane >> 4) * 16;
    auto mmaphase = [&](int bf) {
        uint32_t wH = base + 69632 + bf * 36864;
        uint32_t wL = wH + 18432;
        uint32_t WhH = base + bf * 34816;
        uint32_t WhL = WhH + 17408;
        const uint32_t aoffB = arow * 144 + csel;
        const uint32_t boffB = brow * 272 + csel;
#pragma unroll
        for (int ks = 0; ks < 4; ++ks) {
            uint32_t ah[4], al[4];
            ldsm4(ah, wH + aoffB + ks * 32);
            ldsm4(al, wL + aoffB + ks * 32);
#pragma unroll
            for (int nt = 0; nt < 8; ++nt) {
                uint32_t bh[4], bl[4];
                ldsm4t(bh, WhH + boffB + ks * 16 * 272 + nt * 32);
                ldsm4t(bl, WhL + boffB + ks * 16 * 272 + nt * 32);
                mma16816(acc[2 * nt],     ah, bh[0], bh[1]);
                mma16816(acc[2 * nt],     al, bh[0], bh[1]);
                mma16816(acc[2 * nt],     ah, bl[0], bl[1]);
                mma16816(acc[2 * nt + 1], ah, bh[2], bh[3]);
                mma16816(acc[2 * nt + 1], al, bh[2], bh[3]);
                mma16816(acc[2 * nt + 1], ah, bl[2], bl[3]);
            }
        }
    };

    // ---- pipeline ----
    stage_wh(0, 0); cpa_commit();
    score(0, 0);
    for (int c = 0; c < 32; ++c) {
        if (c + 1 < 32) {
            stage_wh(c + 1, (c + 1) & 1); cpa_commit();
            score(c + 1, (c + 1) & 1);
            asm volatile("cp.async.wait_group 1;");
        } else {
            asm volatile("cp.async.wait_group 0;");
        }
        __syncthreads();
        mmaphase(c & 1);
        __syncthreads();
    }

    // ---- l row sums ----
#pragma unroll
    for (int r = 0; r < 16; ++r) {
        float v = warpSum(lsum[r]);
        if (lane == 0) lsh[wrp * 16 + r] = v;
    }
    __syncthreads();

    // ---- LN + lrelu + maxpool ----
    // lane holds rows r_lo = wrp*16 + (lane>>2), r_hi = +8; cols nt*8 + (lane&3)*2 +{0,1}
    {
        float S1lo = 0.f, S2lo = 0.f, S1hi = 0.f, S2hi = 0.f;
#pragma unroll
        for (int nt = 0; nt < 16; ++nt) {
            S1lo += acc[nt][0] + acc[nt][1];
            S2lo += acc[nt][0] * acc[nt][0] + acc[nt][1] * acc[nt][1];
            S1hi += acc[nt][2] + acc[nt][3];
            S2hi += acc[nt][2] * acc[nt][2] + acc[nt][3] * acc[nt][3];
        }
#pragma unroll
        for (int o = 1; o <= 2; o <<= 1) {
            S1lo += __shfl_xor_sync(0xffffffffu, S1lo, o);
            S2lo += __shfl_xor_sync(0xffffffffu, S2lo, o);
            S1hi += __shfl_xor_sync(0xffffffffu, S1hi, o);
            S2hi += __shfl_xor_sync(0xffffffffu, S2hi, o);
        }
        float Llo = lsh[wrp * 16 + (lane >> 2)];
        float Lhi = lsh[wrp * 16 + (lane >> 2) + 8];
        float mlo = S1lo * (1.f / Dd);
        float vlo = S2lo * (1.f / Dd) - mlo * mlo;
        float rlo = rsqrtf(vlo + 1e-5f * Llo * Llo);
        float mhi = S1hi * (1.f / Dd);
        float vhi = S2hi * (1.f / Dd) - mhi * mhi;
        float rhi = rsqrtf(vhi + 1e-5f * Lhi * Lhi);

#pragma unroll
        for (int nt = 0; nt < 16; ++nt) {
            float n0 = lrelu((acc[nt][0] - mlo) * rlo);
            float n1 = lrelu((acc[nt][1] - mlo) * rlo);
            float n2 = lrelu((acc[nt][2] - mhi) * rhi);
            float n3 = lrelu((acc[nt][3] - mhi) * rhi);
            float m0 = fmaxf(n0, n2);
            float m1 = fmaxf(n1, n3);
#pragma unroll
            for (int o = 4; o <= 16; o <<= 1) {
                m0 = fmaxf(m0, __shfl_xor_sync(0xffffffffu, m0, o));
                m1 = fmaxf(m1, __shfl_xor_sync(0xffffffffu, m1, o));
            }
            if (lane < 4) {
                pm[wrp][nt * 8 + lane * 2]     = m0;
                pm[wrp][nt * 8 + lane * 2 + 1] = m1;
            }
        }
    }
    __syncthreads();
    if (t < 128) {
        float mx = pm[0][t];
#pragma unroll
        for (int w2 = 1; w2 < 8; ++w2) mx = fmaxf(mx, pm[w2][t]);
        atomicMaxFloat(&g_pooled[(b << 7) + t], mx);
    }
}

// ---------------- K3: head + log_softmax ----------------
__global__ void k3_out(const float* __restrict__ W2, const float* __restrict__ b2,
                       float* __restrict__ out)
{
    const int t = threadIdx.x, b = t >> 5, lane = t & 31;
    if (b < Bb) {
        float p0 = 0.f, p1 = 0.f;
        for (int d = lane; d < Dd; d += 32) {
            float pv = g_pooled[b * Dd + d];
            p0 += pv * W2[d];
            p1 += pv * W2[Dd + d];
        }
        p0 = warpSum(p0);
        p1 = warpSum(p1);
        if (lane == 0) {
            float o0 = p0 + b2[0], o1 = p1 + b2[1];
            float m = fmaxf(o0, o1);
            float lse = m + logf(expf(o0 - m) + expf(o1 - m));
            out[b * 2 + 0] = o0 - lse;
            out[b * 2 + 1] = o1 - lse;
        }
    }
}

// ---------------- launch ----------------
extern "C" void kernel_launch(void* const* d_in, const int* in_sizes, int n_in,
                              void* d_out, int out_size)
{
    const float* h   = (const float*)d_in[0];
    const int*   adj = (const int*)  d_in[1];
    const float* W1  = (const float*)d_in[2];
    const float* b1  = (const float*)d_in[3];
    const float* Wg  = (const float*)d_in[4];
    const float* bg  = (const float*)d_in[5];
    const float* a1  = (const float*)d_in[6];
    const float* a2  = (const float*)d_in[7];
    const float* W2  = (const float*)d_in[8];
    const float* b2  = (const float*)d_in[9];
    float* out = (float*)d_out;

    const int smem_k1 = 148480;
    const int smem_k2 = 143360;
    cudaFuncSetAttribute(k1, cudaFuncAttributeMaxDynamicSharedMemorySize, smem_k1);
    cudaFuncSetAttribute(k2_attn, cudaFuncAttributeMaxDynamicSharedMemorySize, smem_k2);

    k_init<<<1, 1024>>>();
    k1<<<128, 512, smem_k1>>>(h, W1, b1, Wg, bg, a1, a2);
    k1c<<<32, 512>>>();
    k2_attn<<<128, 256, smem_k2>>>(adj);
    k3_out<<<1, 256>>>(W2, b2, out);
}

// round 10
// speedup vs baseline: 4.2234x; 1.5319x over previous
#include <cuda_runtime.h>
#include <cuda_fp16.h>
#include <cstdint>

#define Bb 8
#define Nn 2048
#define Dd 128
#define Fin 10
#define ALPHA 0.02f
typedef unsigned long long ull;

// ---------------- device scratch ----------------
__device__ __align__(16) __half g_Whh[Bb * Nn * Dd];   // 4MB fp16 Wh
__device__ float g_e1[Bb * Nn];
__device__ float g_e2[Bb * Nn];
__device__ float g_P[Bb * Nn];
__device__ float g_R[Bb * Nn];
__device__ __align__(16) float4 g_QS[Bb * Nn];         // (e2, Q, S, 0)
__device__ float g_e2max[Bb];
__device__ float g_pooled[Bb * Dd];

// ---------------- helpers ----------------
__device__ __forceinline__ float warpSum(float v) {
#pragma unroll
    for (int o = 16; o > 0; o >>= 1) v += __shfl_xor_sync(0xffffffffu, v, o);
    return v;
}
__device__ __forceinline__ float lrelu(float x) { return fmaxf(x, ALPHA * x); }
__device__ __forceinline__ void atomicMaxFloat(float* a, float v) {
    if (v >= 0.f) atomicMax((int*)a, __float_as_int(v));
    else          atomicMin((unsigned int*)a, __float_as_uint(v));
}
__device__ __forceinline__ void ffma2(ull& a, ull b, ull c) {
    asm("fma.rn.f32x2 %0, %1, %2, %0;" : "+l"(a) : "l"(b), "l"(c));
}
__device__ __forceinline__ ull packf2(float v) {
    ull r; asm("mov.b64 %0, {%1, %1};" : "=l"(r) : "f"(v)); return r;
}
__device__ __forceinline__ uint32_t smem_u32(const void* p) {
    uint32_t a;
    asm("{ .reg .u64 t; cvta.to.shared.u64 t, %1; cvt.u32.u64 %0, t; }" : "=r"(a) : "l"(p));
    return a;
}
__device__ __forceinline__ void ldsm4(uint32_t* r, uint32_t a) {
    asm volatile("ldmatrix.sync.aligned.m8n8.x4.shared.b16 {%0,%1,%2,%3}, [%4];"
        : "=r"(r[0]), "=r"(r[1]), "=r"(r[2]), "=r"(r[3]) : "r"(a));
}
__device__ __forceinline__ void ldsm4t(uint32_t* r, uint32_t a) {
    asm volatile("ldmatrix.sync.aligned.m8n8.x4.trans.shared.b16 {%0,%1,%2,%3}, [%4];"
        : "=r"(r[0]), "=r"(r[1]), "=r"(r[2]), "=r"(r[3]) : "r"(a));
}
__device__ __forceinline__ void mma16816(float* d, const uint32_t* a, uint32_t b0, uint32_t b1) {
    asm volatile("mma.sync.aligned.m16n8k16.row.col.f32.f16.f16.f32 "
        "{%0,%1,%2,%3},{%4,%5,%6,%7},{%8,%9},{%0,%1,%2,%3};"
        : "+f"(d[0]), "+f"(d[1]), "+f"(d[2]), "+f"(d[3])
        : "r"(a[0]), "r"(a[1]), "r"(a[2]), "r"(a[3]), "r"(b0), "r"(b1));
}
__device__ __forceinline__ void cpa16(uint32_t dst, const void* src) {
    asm volatile("cp.async.cg.shared.global [%0], [%1], 16;" :: "r"(dst), "l"(src));
}
__device__ __forceinline__ void cpa_commit() { asm volatile("cp.async.commit_group;"); }

// ---------------- K0 ----------------
__global__ void k_init() {
    g_pooled[threadIdx.x] = -3.402823466e38f;
    if (threadIdx.x < Bb) g_e2max[threadIdx.x] = -3.402823466e38f;
}

// ---------------- K1: fc1+LN+lrelu -> Wg GEMM -> e1/e2/e2max -> Wh fp16 ---------
// 128 blocks x 512 threads; block = 128 nodes
__global__ __launch_bounds__(512, 1) void k1(
    const float* __restrict__ h, const float* __restrict__ W1, const float* __restrict__ b1,
    const float* __restrict__ Wg, const float* __restrict__ bg,
    const float* __restrict__ a1, const float* __restrict__ a2)
{
    extern __shared__ __align__(16) float sm[];
    float* wgt = sm;                 // [128 k][132]
    float* xsh = sm + 16896;         // [128 n][129]
    float* hsh = sm + 33408;         // [128 n][10]
    float* w1s = sm + 34688;         // [128 d][10]
    float* b1s = sm + 35968;         // [128]
    float* red = sm + 36096;         // [2][4][128]

    const int t = threadIdx.x, lane = t & 31, wrp = t >> 5;
    const int n0 = blockIdx.x * 128;
    const int b  = blockIdx.x >> 4;

#pragma unroll
    for (int it = 0; it < 32; ++it) {
        int idx = it * 512 + t;
        wgt[(idx & 127) * 132 + (idx >> 7)] = Wg[idx];
    }
#pragma unroll
    for (int idx = t; idx < 128 * Fin; idx += 512) {
        hsh[idx] = h[n0 * Fin + idx];
        w1s[idx] = W1[idx];
    }
    if (t < 128) b1s[t] = b1[t];
    __syncthreads();

    // fc1 + LN + lrelu: thread -> (node n = t&127, dim-quarter qq = t>>7)
    {
        const int n = t & 127, qq = t >> 7;
        float hv[Fin];
#pragma unroll
        for (int f = 0; f < Fin; ++f) hv[f] = hsh[n * Fin + f];
        float xr[32], s1 = 0.f, s2 = 0.f;
#pragma unroll
        for (int k = 0; k < 32; ++k) {
            const int d = qq * 32 + k;
            float x = b1s[d];
#pragma unroll
            for (int f = 0; f < Fin; ++f) x += hv[f] * w1s[d * Fin + f];
            xr[k] = x; s1 += x; s2 += x * x;
        }
        red[qq * 128 + n] = s1;
        red[512 + qq * 128 + n] = s2;
        __syncthreads();
        float S1 = red[n] + red[128 + n] + red[256 + n] + red[384 + n];
        float S2 = red[512 + n] + red[640 + n] + red[768 + n] + red[896 + n];
        float mean = S1 * (1.f / Dd);
        float var  = S2 * (1.f / Dd) - mean * mean;
        float rstd = rsqrtf(var + 1e-5f);
#pragma unroll
        for (int k = 0; k < 32; ++k)
            xsh[n * 129 + qq * 32 + k] = lrelu((xr[k] - mean) * rstd);
    }
    __syncthreads();

    // GEMM: warp -> 8 nodes, lane -> dims 4*lane..+3
    ull acc[8][2];
#pragma unroll
    for (int n = 0; n < 8; ++n) { acc[n][0] = 0ull; acc[n][1] = 0ull; }
    for (int k = 0; k < 128; ++k) {
        ulonglong2 wv = *(const ulonglong2*)&wgt[k * 132 + lane * 4];
#pragma unroll
        for (int n = 0; n < 8; ++n) {
            ull xx = packf2(xsh[(wrp * 8 + n) * 129 + k]);
            ffma2(acc[n][0], xx, wv.x);
            ffma2(acc[n][1], xx, wv.y);
        }
    }

    const float4 bgv = ((const float4*)bg)[lane];
    const float4 a1v = ((const float4*)a1)[lane];
    const float4 a2v = ((const float4*)a2)[lane];
    float e2mx = -3.402823466e38f;
#pragma unroll
    for (int n = 0; n < 8; ++n) {
        const int node = n0 + wrp * 8 + n;
        float2 lo = *(float2*)&acc[n][0];
        float2 hi = *(float2*)&acc[n][1];
        float v0 = lo.x + bgv.x, v1 = lo.y + bgv.y;
        float v2 = hi.x + bgv.z, v3 = hi.y + bgv.w;

        ((__half2*)g_Whh)[node * 64 + lane * 2]     = __floats2half2_rn(v0, v1);
        ((__half2*)g_Whh)[node * 64 + lane * 2 + 1] = __floats2half2_rn(v2, v3);

        float p1 = warpSum(v0 * a1v.x + v1 * a1v.y + v2 * a1v.z + v3 * a1v.w);
        float p2 = warpSum(v0 * a2v.x + v1 * a2v.y + v2 * a2v.z + v3 * a2v.w);
        if (lane == 0) {
            g_e1[node] = p1;
            g_e2[node] = p2;
            e2mx = fmaxf(e2mx, p2);
        }
    }
    if (lane == 0) atomicMaxFloat(&g_e2max[b], e2mx);
}

// ---------------- K1c: factorized softmax terms ----------------
__global__ void k1c() {
    const int idx = blockIdx.x * 512 + threadIdx.x;     // 16384 nodes
    const int b = idx >> 11;
    float e1 = g_e1[idx], e2 = g_e2[idx], em = g_e2max[b];
    float m = lrelu(e1 + em);
    g_P[idx] = __expf(e1 + em - m);
    g_R[idx] = __expf(ALPHA * (e1 + em) - m);
    float Q = __expf(e2 - em);
    float S = __expf(ALPHA * (e2 - em));
    g_QS[idx] = make_float4(e2, Q, S, 0.f);
}

// ---------------- K2: masked attention via mma.sync ----------------
// 128 blocks x 256 threads (8 warps); block = (b, 128 i-rows); 32 chunks of 64 j.
// smem dyn (bytes): WhH[buf] = buf*17408 (64r x 136h);
//                   wH[buf]  = 34816 + buf*18432 (128r x 72h)
__global__ __launch_bounds__(256, 1) void k2_attn(const int* __restrict__ adj)
{
    extern __shared__ __align__(16) char smd[];
    __shared__ float e1s[128], Ps[128], Rs[128], lsh[128];
    __shared__ float pm[8][128];

    const int t = threadIdx.x, lane = t & 31, wrp = t >> 5;
    const int b  = blockIdx.x >> 4;
    const int i0 = (blockIdx.x & 15) << 7;
    const uint32_t base = smem_u32(smd);

    if (t < 128) {
        int idx = (b << 11) + i0 + t;
        e1s[t] = g_e1[idx];
        Ps[t]  = g_P[idx];
        Rs[t]  = g_R[idx];
    }
    __syncthreads();

    float acc[16][4];
#pragma unroll
    for (int i = 0; i < 16; ++i)
#pragma unroll
        for (int q = 0; q < 4; ++q) acc[i][q] = 0.f;
    float lsum[16];
#pragma unroll
    for (int r = 0; r < 16; ++r) lsum[r] = 0.f;

    // ---- stage Wh(chunk) into buf via cp.async (hi only, 16KB) ----
    auto stage_wh = [&](int cc, int bf) {
        const char* sH = (const char*)(g_Whh + ((size_t)((b << 11) + cc * 64) << 7));
        uint32_t dH = base + bf * 17408;
#pragma unroll
        for (int q = 0; q < 4; ++q) {
            int task = q * 256 + t;             // 0..1023
            int row = task >> 4, seg = task & 15;
            cpa16(dH + row * 272 + seg * 16, sH + row * 256 + seg * 16);
        }
    };

    // ---- score: warp -> rows wrp*16..+16; lane -> j = 2*lane, 2*lane+1 ----
    auto score = [&](int cc, int bf) {
        uint32_t wOff = 34816 + bf * 18432;
        const float4 qs0 = g_QS[(b << 11) + cc * 64 + 2 * lane];
        const float4 qs1 = g_QS[(b << 11) + cc * 64 + 2 * lane + 1];
        const int rbase = wrp * 16;
        const int2* ap = (const int2*)(adj + ((size_t)((b << 11) + i0 + rbase) << 11) + cc * 64) + lane;
#pragma unroll
        for (int rb = 0; rb < 16; rb += 4) {
            int2 av[4];
#pragma unroll
            for (int q = 0; q < 4; ++q) av[q] = ap[(size_t)(rb + q) << 10];
#pragma unroll
            for (int q = 0; q < 4; ++q) {
                const int r = rb + q;
                const int row = rbase + r;
                float e1r = e1s[row], Pr = Ps[row], Rr = Rs[row];
                float f0 = (e1r + qs0.x >= 0.f) ? Pr * qs0.y : Rr * qs0.z;
                float f1 = (e1r + qs1.x >= 0.f) ? Pr * qs1.y : Rr * qs1.z;
                float w0 = (av[q].x != 0) ? f0 : 0.f;
                float w1 = (av[q].y != 0) ? f1 : 0.f;
                lsum[r] += w0 + w1;
                *(__half2*)(smd + wOff + row * 144 + lane * 4) = __floats2half2_rn(w0, w1);
            }
        }
    };

    // ---- mma phase (single fp16 product) ----
    const uint32_t arow = wrp * 16 + ((lane >> 3) & 1) * 8 + (lane & 7);
    const uint32_t brow = ((lane >> 3) & 1) * 8 + (lane & 7);
    const uint32_t csel = (lane >> 4) * 16;
    auto mmaphase = [&](int bf) {
        uint32_t wH  = base + 34816 + bf * 18432;
        uint32_t WhH = base + bf * 17408;
        const uint32_t aoffB = arow * 144 + csel;
        const uint32_t boffB = brow * 272 + csel;
#pragma unroll
        for (int ks = 0; ks < 4; ++ks) {
            uint32_t ah[4];
            ldsm4(ah, wH + aoffB + ks * 32);
#pragma unroll
            for (int nt = 0; nt < 8; ++nt) {
                uint32_t bh[4];
                ldsm4t(bh, WhH + boffB + ks * 16 * 272 + nt * 32);
                mma16816(acc[2 * nt],     ah, bh[0], bh[1]);
                mma16816(acc[2 * nt + 1], ah, bh[2], bh[3]);
            }
        }
    };

    // ---- pipeline: stage(c+1); mma(c); score(c+1); wait; sync ----
    stage_wh(0, 0); cpa_commit();
    score(0, 0);
    asm volatile("cp.async.wait_group 0;");
    __syncthreads();
    for (int c = 0; c < 32; ++c) {
        if (c + 1 < 32) { stage_wh(c + 1, (c + 1) & 1); cpa_commit(); }
        mmaphase(c & 1);
        if (c + 1 < 32) score(c + 1, (c + 1) & 1);
        asm volatile("cp.async.wait_group 0;");
        __syncthreads();
    }

    // ---- l row sums ----
#pragma unroll
    for (int r = 0; r < 16; ++r) {
        float v = warpSum(lsum[r]);
        if (lane == 0) lsh[wrp * 16 + r] = v;
    }
    __syncthreads();

    // ---- LN + lrelu + maxpool ----
    {
        float S1lo = 0.f, S2lo = 0.f, S1hi = 0.f, S2hi = 0.f;
#pragma unroll
        for (int nt = 0; nt < 16; ++nt) {
            S1lo += acc[nt][0] + acc[nt][1];
            S2lo += acc[nt][0] * acc[nt][0] + acc[nt][1] * acc[nt][1];
            S1hi += acc[nt][2] + acc[nt][3];
            S2hi += acc[nt][2] * acc[nt][2] + acc[nt][3] * acc[nt][3];
        }
#pragma unroll
        for (int o = 1; o <= 2; o <<= 1) {
            S1lo += __shfl_xor_sync(0xffffffffu, S1lo, o);
            S2lo += __shfl_xor_sync(0xffffffffu, S2lo, o);
            S1hi += __shfl_xor_sync(0xffffffffu, S1hi, o);
            S2hi += __shfl_xor_sync(0xffffffffu, S2hi, o);
        }
        float Llo = lsh[wrp * 16 + (lane >> 2)];
        float Lhi = lsh[wrp * 16 + (lane >> 2) + 8];
        float mlo = S1lo * (1.f / Dd);
        float vlo = S2lo * (1.f / Dd) - mlo * mlo;
        float rlo = rsqrtf(vlo + 1e-5f * Llo * Llo);
        float mhi = S1hi * (1.f / Dd);
        float vhi = S2hi * (1.f / Dd) - mhi * mhi;
        float rhi = rsqrtf(vhi + 1e-5f * Lhi * Lhi);

#pragma unroll
        for (int nt = 0; nt < 16; ++nt) {
            float n0 = lrelu((acc[nt][0] - mlo) * rlo);
            float n1 = lrelu((acc[nt][1] - mlo) * rlo);
            float n2 = lrelu((acc[nt][2] - mhi) * rhi);
            float n3 = lrelu((acc[nt][3] - mhi) * rhi);
            float m0 = fmaxf(n0, n2);
            float m1 = fmaxf(n1, n3);
#pragma unroll
            for (int o = 4; o <= 16; o <<= 1) {
                m0 = fmaxf(m0, __shfl_xor_sync(0xffffffffu, m0, o));
                m1 = fmaxf(m1, __shfl_xor_sync(0xffffffffu, m1, o));
            }
            if (lane < 4) {
                pm[wrp][nt * 8 + lane * 2]     = m0;
                pm[wrp][nt * 8 + lane * 2 + 1] = m1;
            }
        }
    }
    __syncthreads();
    if (t < 128) {
        float mx = pm[0][t];
#pragma unroll
        for (int w2 = 1; w2 < 8; ++w2) mx = fmaxf(mx, pm[w2][t]);
        atomicMaxFloat(&g_pooled[(b << 7) + t], mx);
    }
}

// ---------------- K3: head + log_softmax ----------------
__global__ void k3_out(const float* __restrict__ W2, const float* __restrict__ b2,
                       float* __restrict__ out)
{
    const int t = threadIdx.x, b = t >> 5, lane = t & 31;
    if (b < Bb) {
        float p0 = 0.f, p1 = 0.f;
        for (int d = lane; d < Dd; d += 32) {
            float pv = g_pooled[b * Dd + d];
            p0 += pv * W2[d];
            p1 += pv * W2[Dd + d];
        }
        p0 = warpSum(p0);
        p1 = warpSum(p1);
        if (lane == 0) {
            float o0 = p0 + b2[0], o1 = p1 + b2[1];
            float m = fmaxf(o0, o1);
            float lse = m + logf(expf(o0 - m) + expf(o1 - m));
            out[b * 2 + 0] = o0 - lse;
            out[b * 2 + 1] = o1 - lse;
        }
    }
}

// ---------------- launch ----------------
extern "C" void kernel_launch(void* const* d_in, const int* in_sizes, int n_in,
                              void* d_out, int out_size)
{
    const float* h   = (const float*)d_in[0];
    const int*   adj = (const int*)  d_in[1];
    const float* W1  = (const float*)d_in[2];
    const float* b1  = (const float*)d_in[3];
    const float* Wg  = (const float*)d_in[4];
    const float* bg  = (const float*)d_in[5];
    const float* a1  = (const float*)d_in[6];
    const float* a2  = (const float*)d_in[7];
    const float* W2  = (const float*)d_in[8];
    const float* b2  = (const float*)d_in[9];
    float* out = (float*)d_out;

    const int smem_k1 = 148480;
    const int smem_k2 = 34816 + 2 * 18432;   // 71680
    cudaFuncSetAttribute(k1, cudaFuncAttributeMaxDynamicSharedMemorySize, smem_k1);
    cudaFuncSetAttribute(k2_attn, cudaFuncAttributeMaxDynamicSharedMemorySize, smem_k2);

    k_init<<<1, 1024>>>();
    k1<<<128, 512, smem_k1>>>(h, W1, b1, Wg, bg, a1, a2);
    k1c<<<32, 512>>>();
    k2_attn<<<128, 256, smem_k2>>>(adj);
    k3_out<<<1, 256>>>(W2, b2, out);
}

// round 11
// speedup vs baseline: 5.5332x; 1.3101x over previous
#include <cuda_runtime.h>
#include <cuda_fp16.h>
#include <cstdint>

#define Bb 8
#define Nn 2048
#define Dd 128
#define Fin 10
#define ALPHA 0.02f
typedef unsigned long long ull;

// ---------------- device scratch ----------------
__device__ __align__(16) __half g_Whh[Bb * Nn * Dd];   // 4MB fp16 Wh
__device__ float g_e1[Bb * Nn];
__device__ float g_e2[Bb * Nn];
__device__ float g_P[Bb * Nn];
__device__ float g_R[Bb * Nn];
__device__ __align__(16) float4 g_QS[Bb * Nn];         // (e2, Q, S, 0)
__device__ float g_e2max[Bb];
__device__ float g_pooled[Bb * Dd];

// ---------------- helpers ----------------
__device__ __forceinline__ float warpSum(float v) {
#pragma unroll
    for (int o = 16; o > 0; o >>= 1) v += __shfl_xor_sync(0xffffffffu, v, o);
    return v;
}
__device__ __forceinline__ float lrelu(float x) { return fmaxf(x, ALPHA * x); }
__device__ __forceinline__ void atomicMaxFloat(float* a, float v) {
    if (v >= 0.f) atomicMax((int*)a, __float_as_int(v));
    else          atomicMin((unsigned int*)a, __float_as_uint(v));
}
__device__ __forceinline__ void ffma2(ull& a, ull b, ull c) {
    asm("fma.rn.f32x2 %0, %1, %2, %0;" : "+l"(a) : "l"(b), "l"(c));
}
__device__ __forceinline__ ull packf2(float v) {
    ull r; asm("mov.b64 %0, {%1, %1};" : "=l"(r) : "f"(v)); return r;
}
__device__ __forceinline__ uint32_t smem_u32(const void* p) {
    uint32_t a;
    asm("{ .reg .u64 t; cvta.to.shared.u64 t, %1; cvt.u32.u64 %0, t; }" : "=r"(a) : "l"(p));
    return a;
}
__device__ __forceinline__ void ldsm4(uint32_t* r, uint32_t a) {
    asm volatile("ldmatrix.sync.aligned.m8n8.x4.shared.b16 {%0,%1,%2,%3}, [%4];"
        : "=r"(r[0]), "=r"(r[1]), "=r"(r[2]), "=r"(r[3]) : "r"(a));
}
__device__ __forceinline__ void ldsm4t(uint32_t* r, uint32_t a) {
    asm volatile("ldmatrix.sync.aligned.m8n8.x4.trans.shared.b16 {%0,%1,%2,%3}, [%4];"
        : "=r"(r[0]), "=r"(r[1]), "=r"(r[2]), "=r"(r[3]) : "r"(a));
}
__device__ __forceinline__ void mma16816(float* d, const uint32_t* a, uint32_t b0, uint32_t b1) {
    asm volatile("mma.sync.aligned.m16n8k16.row.col.f32.f16.f16.f32 "
        "{%0,%1,%2,%3},{%4,%5,%6,%7},{%8,%9},{%0,%1,%2,%3};"
        : "+f"(d[0]), "+f"(d[1]), "+f"(d[2]), "+f"(d[3])
        : "r"(a[0]), "r"(a[1]), "r"(a[2]), "r"(a[3]), "r"(b0), "r"(b1));
}
__device__ __forceinline__ void cpa16(uint32_t dst, const void* src) {
    asm volatile("cp.async.cg.shared.global [%0], [%1], 16;" :: "r"(dst), "l"(src));
}
__device__ __forceinline__ void cpa_commit() { asm volatile("cp.async.commit_group;"); }

// ---------------- K0 ----------------
__global__ void k_init() {
    g_pooled[threadIdx.x] = -3.402823466e38f;
    if (threadIdx.x < Bb) g_e2max[threadIdx.x] = -3.402823466e38f;
}

// ---------------- K1: fc1+LN+lrelu -> Wg GEMM -> e1/e2/e2max -> Wh fp16 ---------
// 128 blocks x 512 threads; block = 128 nodes
__global__ __launch_bounds__(512, 1) void k1(
    const float* __restrict__ h, const float* __restrict__ W1, const float* __restrict__ b1,
    const float* __restrict__ Wg, const float* __restrict__ bg,
    const float* __restrict__ a1, const float* __restrict__ a2)
{
    extern __shared__ __align__(16) float sm[];
    float* wgt = sm;                 // [128 k][132]
    float* xsh = sm + 16896;         // [128 n][129]
    float* hsh = sm + 33408;         // [128 n][10]
    float* w1s = sm + 34688;         // [128 d][10]
    float* b1s = sm + 35968;         // [128]
    float* red = sm + 36096;         // [2][4][128]

    const int t = threadIdx.x, lane = t & 31, wrp = t >> 5;
    const int n0 = blockIdx.x * 128;
    const int b  = blockIdx.x >> 4;

#pragma unroll
    for (int it = 0; it < 32; ++it) {
        int idx = it * 512 + t;
        wgt[(idx & 127) * 132 + (idx >> 7)] = Wg[idx];
    }
#pragma unroll
    for (int idx = t; idx < 128 * Fin; idx += 512) {
        hsh[idx] = h[n0 * Fin + idx];
        w1s[idx] = W1[idx];
    }
    if (t < 128) b1s[t] = b1[t];
    __syncthreads();

    {
        const int n = t & 127, qq = t >> 7;
        float hv[Fin];
#pragma unroll
        for (int f = 0; f < Fin; ++f) hv[f] = hsh[n * Fin + f];
        float xr[32], s1 = 0.f, s2 = 0.f;
#pragma unroll
        for (int k = 0; k < 32; ++k) {
            const int d = qq * 32 + k;
            float x = b1s[d];
#pragma unroll
            for (int f = 0; f < Fin; ++f) x += hv[f] * w1s[d * Fin + f];
            xr[k] = x; s1 += x; s2 += x * x;
        }
        red[qq * 128 + n] = s1;
        red[512 + qq * 128 + n] = s2;
        __syncthreads();
        float S1 = red[n] + red[128 + n] + red[256 + n] + red[384 + n];
        float S2 = red[512 + n] + red[640 + n] + red[768 + n] + red[896 + n];
        float mean = S1 * (1.f / Dd);
        float var  = S2 * (1.f / Dd) - mean * mean;
        float rstd = rsqrtf(var + 1e-5f);
#pragma unroll
        for (int k = 0; k < 32; ++k)
            xsh[n * 129 + qq * 32 + k] = lrelu((xr[k] - mean) * rstd);
    }
    __syncthreads();

    ull acc[8][2];
#pragma unroll
    for (int n = 0; n < 8; ++n) { acc[n][0] = 0ull; acc[n][1] = 0ull; }
    for (int k = 0; k < 128; ++k) {
        ulonglong2 wv = *(const ulonglong2*)&wgt[k * 132 + lane * 4];
#pragma unroll
        for (int n = 0; n < 8; ++n) {
            ull xx = packf2(xsh[(wrp * 8 + n) * 129 + k]);
            ffma2(acc[n][0], xx, wv.x);
            ffma2(acc[n][1], xx, wv.y);
        }
    }

    const float4 bgv = ((const float4*)bg)[lane];
    const float4 a1v = ((const float4*)a1)[lane];
    const float4 a2v = ((const float4*)a2)[lane];
    float e2mx = -3.402823466e38f;
#pragma unroll
    for (int n = 0; n < 8; ++n) {
        const int node = n0 + wrp * 8 + n;
        float2 lo = *(float2*)&acc[n][0];
        float2 hi = *(float2*)&acc[n][1];
        float v0 = lo.x + bgv.x, v1 = lo.y + bgv.y;
        float v2 = hi.x + bgv.z, v3 = hi.y + bgv.w;

        ((__half2*)g_Whh)[node * 64 + lane * 2]     = __floats2half2_rn(v0, v1);
        ((__half2*)g_Whh)[node * 64 + lane * 2 + 1] = __floats2half2_rn(v2, v3);

        float p1 = warpSum(v0 * a1v.x + v1 * a1v.y + v2 * a1v.z + v3 * a1v.w);
        float p2 = warpSum(v0 * a2v.x + v1 * a2v.y + v2 * a2v.z + v3 * a2v.w);
        if (lane == 0) {
            g_e1[node] = p1;
            g_e2[node] = p2;
            e2mx = fmaxf(e2mx, p2);
        }
    }
    if (lane == 0) atomicMaxFloat(&g_e2max[b], e2mx);
}

// ---------------- K1c: factorized softmax terms ----------------
__global__ void k1c() {
    const int idx = blockIdx.x * 512 + threadIdx.x;
    const int b = idx >> 11;
    float e1 = g_e1[idx], e2 = g_e2[idx], em = g_e2max[b];
    float m = lrelu(e1 + em);
    g_P[idx] = __expf(e1 + em - m);
    g_R[idx] = __expf(ALPHA * (e1 + em) - m);
    float Q = __expf(e2 - em);
    float S = __expf(ALPHA * (e2 - em));
    g_QS[idx] = make_float4(e2, Q, S, 0.f);
}

// ---------------- K2: masked attention via mma.sync ----------------
// 256 blocks x 128 threads (4 warps); block = (b, 64 i-rows); 32 chunks of 64 j.
// smem dyn: WhH[2] @ 0 / 17408 (64r x 272B); adj[2] @ 34816 / 51200 (64r x 256B);
//           w @ 67584 (64r x 144B). Total 76800 B.
__global__ __launch_bounds__(128, 2) void k2_attn(const int* __restrict__ adj)
{
    extern __shared__ __align__(16) char smd[];
    __shared__ float e1s[64], Ps[64], Rs[64], lsh[64];
    __shared__ float pm[4][128];

    const int t = threadIdx.x, lane = t & 31, wrp = t >> 5;
    const int b  = blockIdx.x >> 5;
    const int i0 = (blockIdx.x & 31) << 6;
    const uint32_t base = smem_u32(smd);

    if (t < 64) {
        int idx = (b << 11) + i0 + t;
        e1s[t] = g_e1[idx];
        Ps[t]  = g_P[idx];
        Rs[t]  = g_R[idx];
    }

    float acc[16][4];
#pragma unroll
    for (int i = 0; i < 16; ++i)
#pragma unroll
        for (int q = 0; q < 4; ++q) acc[i][q] = 0.f;
    float lsum[16];
#pragma unroll
    for (int r = 0; r < 16; ++r) lsum[r] = 0.f;

    // ---- stage Wh(chunk): 64 j-rows x 256B -> 272B-stride smem ----
    auto stage_wh = [&](int cc, int bf) {
        const char* sH = (const char*)(g_Whh + ((size_t)((b << 11) + cc * 64) << 7));
        uint32_t dH = base + bf * 17408;
#pragma unroll
        for (int q = 0; q < 8; ++q) {
            int task = q * 128 + t;             // 0..1023
            int row = task >> 4, seg = task & 15;
            cpa16(dH + row * 272 + seg * 16, sH + row * 256 + seg * 16);
        }
    };
    // ---- stage adj(chunk): 64 i-rows x 256B ----
    auto stage_adj = [&](int cc, int bf) {
        const char* sA = (const char*)(adj + ((size_t)((b << 11) + i0) << 11) + cc * 64);
        uint32_t dA = base + 34816 + bf * 16384;
#pragma unroll
        for (int q = 0; q < 8; ++q) {
            int task = q * 128 + t;
            int row = task >> 4, seg = task & 15;
            cpa16(dA + row * 256 + seg * 16, sA + (size_t)row * 8192 + seg * 16);
        }
    };

    // ---- score: warp -> rows wrp*16..+16; lane -> j = 2*lane, 2*lane+1 ----
    auto score = [&](int cc, int bf) {
        const uint32_t aOff = 34816 + bf * 16384;
        const float4 qs0 = g_QS[(b << 11) + cc * 64 + 2 * lane];
        const float4 qs1 = g_QS[(b << 11) + cc * 64 + 2 * lane + 1];
        const int rbase = wrp * 16;
#pragma unroll
        for (int r = 0; r < 16; ++r) {
            const int row = rbase + r;
            int2 av = *(const int2*)(smd + aOff + row * 256 + lane * 8);
            float e1r = e1s[row], Pr = Ps[row], Rr = Rs[row];
            float f0 = (e1r + qs0.x >= 0.f) ? Pr * qs0.y : Rr * qs0.z;
            float f1 = (e1r + qs1.x >= 0.f) ? Pr * qs1.y : Rr * qs1.z;
            float w0 = (av.x != 0) ? f0 : 0.f;
            float w1 = (av.y != 0) ? f1 : 0.f;
            lsum[r] += w0 + w1;
            *(__half2*)(smd + 67584 + row * 144 + lane * 4) = __floats2half2_rn(w0, w1);
        }
    };

    // ---- mma (single fp16 product) ----
    const uint32_t arow = wrp * 16 + ((lane >> 3) & 1) * 8 + (lane & 7);
    const uint32_t brow = ((lane >> 3) & 1) * 8 + (lane & 7);
    const uint32_t csel = (lane >> 4) * 16;
    auto mmaphase = [&](int bf) {
        uint32_t wH  = base + 67584;
        uint32_t WhH = base + bf * 17408;
        const uint32_t aoffB = arow * 144 + csel;
        const uint32_t boffB = brow * 272 + csel;
#pragma unroll
        for (int ks = 0; ks < 4; ++ks) {
            uint32_t ah[4];
            ldsm4(ah, wH + aoffB + ks * 32);
#pragma unroll
            for (int nt = 0; nt < 8; ++nt) {
                uint32_t bh[4];
                ldsm4t(bh, WhH + boffB + ks * 16 * 272 + nt * 32);
                mma16816(acc[2 * nt],     ah, bh[0], bh[1]);
                mma16816(acc[2 * nt + 1], ah, bh[2], bh[3]);
            }
        }
    };

    // ---- pipeline: wait(c); sync; issue(c+1); score(c); sync; mma(c) ----
    stage_wh(0, 0); stage_adj(0, 0); cpa_commit();
    for (int c = 0; c < 32; ++c) {
        const int p = c & 1;
        asm volatile("cp.async.wait_group 0;");
        __syncthreads();                       // bufs(c) ready; mma(c-1) done everywhere
        if (c + 1 < 32) { stage_wh(c + 1, p ^ 1); stage_adj(c + 1, p ^ 1); cpa_commit(); }
        score(c, p);
        __syncthreads();                       // w(c) visible
        mmaphase(p);
    }

    // ---- l row sums ----
#pragma unroll
    for (int r = 0; r < 16; ++r) {
        float v = warpSum(lsum[r]);
        if (lane == 0) lsh[wrp * 16 + r] = v;
    }
    __syncthreads();

    // ---- LN + lrelu + maxpool ----
    {
        float S1lo = 0.f, S2lo = 0.f, S1hi = 0.f, S2hi = 0.f;
#pragma unroll
        for (int nt = 0; nt < 16; ++nt) {
            S1lo += acc[nt][0] + acc[nt][1];
            S2lo += acc[nt][0] * acc[nt][0] + acc[nt][1] * acc[nt][1];
            S1hi += acc[nt][2] + acc[nt][3];
            S2hi += acc[nt][2] * acc[nt][2] + acc[nt][3] * acc[nt][3];
        }
#pragma unroll
        for (int o = 1; o <= 2; o <<= 1) {
            S1lo += __shfl_xor_sync(0xffffffffu, S1lo, o);
            S2lo += __shfl_xor_sync(0xffffffffu, S2lo, o);
            S1hi += __shfl_xor_sync(0xffffffffu, S1hi, o);
            S2hi += __shfl_xor_sync(0xffffffffu, S2hi, o);
        }
        float Llo = lsh[wrp * 16 + (lane >> 2)];
        float Lhi = lsh[wrp * 16 + (lane >> 2) + 8];
        float mlo = S1lo * (1.f / Dd);
        float vlo = S2lo * (1.f / Dd) - mlo * mlo;
        float rlo = rsqrtf(vlo + 1e-5f * Llo * Llo);
        float mhi = S1hi * (1.f / Dd);
        float vhi = S2hi * (1.f / Dd) - mhi * mhi;
        float rhi = rsqrtf(vhi + 1e-5f * Lhi * Lhi);

#pragma unroll
        for (int nt = 0; nt < 16; ++nt) {
            float n0 = lrelu((acc[nt][0] - mlo) * rlo);
            float n1 = lrelu((acc[nt][1] - mlo) * rlo);
            float n2 = lrelu((acc[nt][2] - mhi) * rhi);
            float n3 = lrelu((acc[nt][3] - mhi) * rhi);
            float m0 = fmaxf(n0, n2);
            float m1 = fmaxf(n1, n3);
#pragma unroll
            for (int o = 4; o <= 16; o <<= 1) {
                m0 = fmaxf(m0, __shfl_xor_sync(0xffffffffu, m0, o));
                m1 = fmaxf(m1, __shfl_xor_sync(0xffffffffu, m1, o));
            }
            if (lane < 4) {
                pm[wrp][nt * 8 + lane * 2]     = m0;
                pm[wrp][nt * 8 + lane * 2 + 1] = m1;
            }
        }
    }
    __syncthreads();
    if (t < 128) {
        float mx = fmaxf(fmaxf(pm[0][t], pm[1][t]), fmaxf(pm[2][t], pm[3][t]));
        atomicMaxFloat(&g_pooled[(b << 7) + t], mx);
    }
}

// ---------------- K3: head + log_softmax ----------------
__global__ void k3_out(const float* __restrict__ W2, const float* __restrict__ b2,
                       float* __restrict__ out)
{
    const int t = threadIdx.x, b = t >> 5, lane = t & 31;
    if (b < Bb) {
        float p0 = 0.f, p1 = 0.f;
        for (int d = lane; d < Dd; d += 32) {
            float pv = g_pooled[b * Dd + d];
            p0 += pv * W2[d];
            p1 += pv * W2[Dd + d];
        }
        p0 = warpSum(p0);
        p1 = warpSum(p1);
        if (lane == 0) {
            float o0 = p0 + b2[0], o1 = p1 + b2[1];
            float m = fmaxf(o0, o1);
            float lse = m + logf(expf(o0 - m) + expf(o1 - m));
            out[b * 2 + 0] = o0 - lse;
            out[b * 2 + 1] = o1 - lse;
        }
    }
}

// ---------------- launch ----------------
extern "C" void kernel_launch(void* const* d_in, const int* in_sizes, int n_in,
                              void* d_out, int out_size)
{
    const float* h   = (const float*)d_in[0];
    const int*   adj = (const int*)  d_in[1];
    const float* W1  = (const float*)d_in[2];
    const float* b1  = (const float*)d_in[3];
    const float* Wg  = (const float*)d_in[4];
    const float* bg  = (const float*)d_in[5];
    const float* a1  = (const float*)d_in[6];
    const float* a2  = (const float*)d_in[7];
    const float* W2  = (const float*)d_in[8];
    const float* b2  = (const float*)d_in[9];
    float* out = (float*)d_out;

    const int smem_k1 = 148480;
    const int smem_k2 = 76800;
    cudaFuncSetAttribute(k1, cudaFuncAttributeMaxDynamicSharedMemorySize, smem_k1);
    cudaFuncSetAttribute(k2_attn, cudaFuncAttributeMaxDynamicSharedMemorySize, smem_k2);

    k_init<<<1, 1024>>>();
    k1<<<128, 512, smem_k1>>>(h, W1, b1, Wg, bg, a1, a2);
    k1c<<<32, 512>>>();
    k2_attn<<<256, 128, smem_k2>>>(adj);
    k3_out<<<1, 256>>>(W2, b2, out);
}

// round 14
// speedup vs baseline: 5.9053x; 1.0673x over previous
#include <cuda_runtime.h>
#include <cuda_fp16.h>
#include <cstdint>

#define Bb 8
#define Nn 2048
#define Dd 128
#define Fin 10
#define ALPHA 0.02f
typedef unsigned long long ull;

// ---------------- device scratch ----------------
__device__ __align__(16) __half g_Whh[Bb * Nn * Dd];   // 4MB fp16 Wh
__device__ float g_e1[Bb * Nn];
__device__ float g_e2[Bb * Nn];
__device__ float g_P[Bb * Nn];
__device__ float g_R[Bb * Nn];
__device__ __align__(16) float4 g_QS[Bb * Nn];         // (e2, Q, S, 0)
__device__ float g_pooled[Bb * Dd];

// ---------------- helpers ----------------
__device__ __forceinline__ float warpSum(float v) {
#pragma unroll
    for (int o = 16; o > 0; o >>= 1) v += __shfl_xor_sync(0xffffffffu, v, o);
    return v;
}
__device__ __forceinline__ float warpMax(float v) {
#pragma unroll
    for (int o = 16; o > 0; o >>= 1) v = fmaxf(v, __shfl_xor_sync(0xffffffffu, v, o));
    return v;
}
__device__ __forceinline__ float lrelu(float x) { return fmaxf(x, ALPHA * x); }
__device__ __forceinline__ void atomicMaxFloat(float* a, float v) {
    if (v >= 0.f) atomicMax((int*)a, __float_as_int(v));
    else          atomicMin((unsigned int*)a, __float_as_uint(v));
}
__device__ __forceinline__ void ffma2(ull& a, ull b, ull c) {
    asm("fma.rn.f32x2 %0, %1, %2, %0;" : "+l"(a) : "l"(b), "l"(c));
}
__device__ __forceinline__ ull packf2(float v) {
    ull r; asm("mov.b64 %0, {%1, %1};" : "=l"(r) : "f"(v)); return r;
}
__device__ __forceinline__ uint32_t smem_u32(const void* p) {
    uint32_t a;
    asm("{ .reg .u64 t; cvta.to.shared.u64 t, %1; cvt.u32.u64 %0, t; }" : "=r"(a) : "l"(p));
    return a;
}
__device__ __forceinline__ void ldsm4(uint32_t* r, uint32_t a) {
    asm volatile("ldmatrix.sync.aligned.m8n8.x4.shared.b16 {%0,%1,%2,%3}, [%4];"
        : "=r"(r[0]), "=r"(r[1]), "=r"(r[2]), "=r"(r[3]) : "r"(a));
}
__device__ __forceinline__ void ldsm4t(uint32_t* r, uint32_t a) {
    asm volatile("ldmatrix.sync.aligned.m8n8.x4.trans.shared.b16 {%0,%1,%2,%3}, [%4];"
        : "=r"(r[0]), "=r"(r[1]), "=r"(r[2]), "=r"(r[3]) : "r"(a));
}
__device__ __forceinline__ void mma16816(float* d, const uint32_t* a, uint32_t b0, uint32_t b1) {
    asm volatile("mma.sync.aligned.m16n8k16.row.col.f32.f16.f16.f32 "
        "{%0,%1,%2,%3},{%4,%5,%6,%7},{%8,%9},{%0,%1,%2,%3};"
        : "+f"(d[0]), "+f"(d[1]), "+f"(d[2]), "+f"(d[3])
        : "r"(a[0]), "r"(a[1]), "r"(a[2]), "r"(a[3]), "r"(b0), "r"(b1));
}
__device__ __forceinline__ void cpa16(uint32_t dst, const void* src) {
    asm volatile("cp.async.cg.shared.global [%0], [%1], 16;" :: "r"(dst), "l"(src));
}
__device__ __forceinline__ void cpa_commit() { asm volatile("cp.async.commit_group;"); }

// ---------------- K1: fc1+LN+lrelu -> Wg GEMM -> e1/e2 -> Wh fp16 ---------
// 128 blocks x 512 threads; block = 128 nodes
__global__ __launch_bounds__(512, 1) void k1(
    const float* __restrict__ h, const float* __restrict__ W1, const float* __restrict__ b1,
    const float* __restrict__ Wg, const float* __restrict__ bg,
    const float* __restrict__ a1, const float* __restrict__ a2)
{
    extern __shared__ __align__(16) float sm[];
    float* wgt = sm;                 // [128 k][132]
    float* xsh = sm + 16896;         // [128 n][129]
    float* hsh = sm + 33408;         // [128 n][10]
    float* w1s = sm + 34688;         // [128 d][10]
    float* b1s = sm + 35968;         // [128]
    float* red = sm + 36096;         // [2][4][128]

    const int t = threadIdx.x, lane = t & 31, wrp = t >> 5;
    const int n0 = blockIdx.x * 128;

#pragma unroll
    for (int it = 0; it < 32; ++it) {
        int idx = it * 512 + t;
        wgt[(idx & 127) * 132 + (idx >> 7)] = Wg[idx];
    }
#pragma unroll
    for (int idx = t; idx < 128 * Fin; idx += 512) {
        hsh[idx] = h[n0 * Fin + idx];
        w1s[idx] = W1[idx];
    }
    if (t < 128) b1s[t] = b1[t];
    __syncthreads();

    {
        const int n = t & 127, qq = t >> 7;
        float hv[Fin];
#pragma unroll
        for (int f = 0; f < Fin; ++f) hv[f] = hsh[n * Fin + f];
        float xr[32], s1 = 0.f, s2 = 0.f;
#pragma unroll
        for (int k = 0; k < 32; ++k) {
            const int d = qq * 32 + k;
            float x = b1s[d];
#pragma unroll
            for (int f = 0; f < Fin; ++f) x += hv[f] * w1s[d * Fin + f];
            xr[k] = x; s1 += x; s2 += x * x;
        }
        red[qq * 128 + n] = s1;
        red[512 + qq * 128 + n] = s2;
        __syncthreads();
        float S1 = red[n] + red[128 + n] + red[256 + n] + red[384 + n];
        float S2 = red[512 + n] + red[640 + n] + red[768 + n] + red[896 + n];
        float mean = S1 * (1.f / Dd);
        float var  = S2 * (1.f / Dd) - mean * mean;
        float rstd = rsqrtf(var + 1e-5f);
#pragma unroll
        for (int k = 0; k < 32; ++k)
            xsh[n * 129 + qq * 32 + k] = lrelu((xr[k] - mean) * rstd);
    }
    __syncthreads();

    ull acc[8][2];
#pragma unroll
    for (int n = 0; n < 8; ++n) { acc[n][0] = 0ull; acc[n][1] = 0ull; }
    for (int k = 0; k < 128; ++k) {
        ulonglong2 wv = *(const ulonglong2*)&wgt[k * 132 + lane * 4];
#pragma unroll
        for (int n = 0; n < 8; ++n) {
            ull xx = packf2(xsh[(wrp * 8 + n) * 129 + k]);
            ffma2(acc[n][0], xx, wv.x);
            ffma2(acc[n][1], xx, wv.y);
        }
    }

    const float4 bgv = ((const float4*)bg)[lane];
    const float4 a1v = ((const float4*)a1)[lane];
    const float4 a2v = ((const float4*)a2)[lane];
#pragma unroll
    for (int n = 0; n < 8; ++n) {
        const int node = n0 + wrp * 8 + n;
        float2 lo = *(float2*)&acc[n][0];
        float2 hi = *(float2*)&acc[n][1];
        float v0 = lo.x + bgv.x, v1 = lo.y + bgv.y;
        float v2 = hi.x + bgv.z, v3 = hi.y + bgv.w;

        ((__half2*)g_Whh)[node * 64 + lane * 2]     = __floats2half2_rn(v0, v1);
        ((__half2*)g_Whh)[node * 64 + lane * 2 + 1] = __floats2half2_rn(v2, v3);

        float p1 = warpSum(v0 * a1v.x + v1 * a1v.y + v2 * a1v.z + v3 * a1v.w);
        float p2 = warpSum(v0 * a2v.x + v1 * a2v.y + v2 * a2v.z + v3 * a2v.w);
        if (lane == 0) {
            g_e1[node] = p1;
            g_e2[node] = p2;
        }
    }
}

// ---------------- K1c: per-batch e2max reduce + factorized terms + pooled init ------
// 8 blocks (one per batch) x 1024 threads
__global__ __launch_bounds__(1024) void k1c() {
    __shared__ float wmax[32];
    const int b = blockIdx.x, t = threadIdx.x;
    if (t < 128) g_pooled[b * 128 + t] = -3.402823466e38f;
    float e2a = g_e2[b * 2048 + t];
    float e2b = g_e2[b * 2048 + 1024 + t];
    float mx = warpMax(fmaxf(e2a, e2b));
    if ((t & 31) == 0) wmax[t >> 5] = mx;
    __syncthreads();
    if (t < 32) wmax[t] = warpMax(wmax[t]);
    __syncthreads();
    float em = wmax[0];
#pragma unroll
    for (int k = 0; k < 2; ++k) {
        int idx = b * 2048 + k * 1024 + t;
        float e1 = g_e1[idx];
        float e2 = k ? e2b : e2a;
        float m = lrelu(e1 + em);
        g_P[idx] = __expf(e1 + em - m);
        g_R[idx] = __expf(ALPHA * (e1 + em) - m);
        g_QS[idx] = make_float4(e2, __expf(e2 - em), __expf(ALPHA * (e2 - em)), 0.f);
    }
}

// ---------------- K2: masked attention via mma.sync (2x2 warp tiling) ----------------
// 256 blocks x 128 threads (4 warps); block = (b, 64 i-rows); 32 chunks of 64 j.
// Warp: i-half iw=(wrp&1)*32, d-half dw=(wrp>>1)*64.
// smem dyn: WhH[2] @ 0 / 17408 (64r x 272B); adj[2] @ 34816 / 51200 (64r x 256B);
//           w @ 67584 (64r x 144B). Total 76800 B.
__global__ __launch_bounds__(128, 2) void k2_attn(const int* __restrict__ adj)
{
    extern __shared__ __align__(16) char smd[];
    __shared__ float e1s[64], Ps[64], Rs[64], lsh[64];
    __shared__ float red1[64][2], red2[64][2];
    __shared__ float mrs[64][2];                 // (mean, rstd) per row
    __shared__ float pm[4][64];

    const int t = threadIdx.x, lane = t & 31, wrp = t >> 5;
    const int b  = blockIdx.x >> 5;
    const int i0 = (blockIdx.x & 31) << 6;
    const uint32_t base = smem_u32(smd);

    if (t < 64) {
        int idx = (b << 11) + i0 + t;
        e1s[t] = g_e1[idx];
        Ps[t]  = g_P[idx];
        Rs[t]  = g_R[idx];
    }

    float acc[2][8][4];
#pragma unroll
    for (int ib = 0; ib < 2; ++ib)
#pragma unroll
        for (int nt = 0; nt < 8; ++nt)
#pragma unroll
            for (int q = 0; q < 4; ++q) acc[ib][nt][q] = 0.f;
    float lsum[16];
#pragma unroll
    for (int r = 0; r < 16; ++r) lsum[r] = 0.f;

    // ---- stage Wh(chunk): 64 j-rows x 256B -> 272B-stride smem ----
    auto stage_wh = [&](int cc, int bf) {
        const char* sH = (const char*)(g_Whh + ((size_t)((b << 11) + cc * 64) << 7));
        uint32_t dH = base + bf * 17408;
#pragma unroll
        for (int q = 0; q < 8; ++q) {
            int task = q * 128 + t;
            int row = task >> 4, seg = task & 15;
            cpa16(dH + row * 272 + seg * 16, sH + row * 256 + seg * 16);
        }
    };
    // ---- stage adj(chunk): 64 i-rows x 256B ----
    auto stage_adj = [&](int cc, int bf) {
        const char* sA = (const char*)(adj + ((size_t)((b << 11) + i0) << 11) + cc * 64);
        uint32_t dA = base + 34816 + bf * 16384;
#pragma unroll
        for (int q = 0; q < 8; ++q) {
            int task = q * 128 + t;
            int row = task >> 4, seg = task & 15;
            cpa16(dA + row * 256 + seg * 16, sA + (size_t)row * 8192 + seg * 16);
        }
    };

    // ---- score: warp -> rows wrp*16..+16; lane -> j = 2*lane, 2*lane+1 ----
    auto score = [&](int cc, int bf) {
        const uint32_t aOff = 34816 + bf * 16384;
        const float4 qs0 = g_QS[(b << 11) + cc * 64 + 2 * lane];
        const float4 qs1 = g_QS[(b << 11) + cc * 64 + 2 * lane + 1];
        const int rbase = wrp * 16;
#pragma unroll
        for (int r = 0; r < 16; ++r) {
            const int row = rbase + r;
            int2 av = *(const int2*)(smd + aOff + row * 256 + lane * 8);
            float e1r = e1s[row], Pr = Ps[row], Rr = Rs[row];
            float f0 = (e1r + qs0.x >= 0.f) ? Pr * qs0.y : Rr * qs0.z;
            float f1 = (e1r + qs1.x >= 0.f) ? Pr * qs1.y : Rr * qs1.z;
            float w0 = (av.x != 0) ? f0 : 0.f;
            float w1 = (av.y != 0) ? f1 : 0.f;
            lsum[r] += w0 + w1;
            *(__half2*)(smd + 67584 + row * 144 + lane * 4) = __floats2half2_rn(w0, w1);
        }
    };

    // ---- mma: warp covers 32i (iw) x 64d (dw); B frags loaded once, shared by 2 ib ----
    const int iw = (wrp & 1) * 32;
    const int dw = (wrp >> 1) * 64;
    const uint32_t lrr  = ((lane >> 3) & 1) * 8 + (lane & 7);
    const uint32_t csel = (lane >> 4) * 16;
    auto mmaphase = [&](int bf) {
        uint32_t wH  = base + 67584;
        uint32_t WhH = base + bf * 17408;
        const uint32_t aoff0 = (iw + lrr) * 144 + csel;
        const uint32_t aoff1 = (iw + 16 + lrr) * 144 + csel;
        const uint32_t boffB = lrr * 272 + csel + dw * 2;
#pragma unroll
        for (int ks = 0; ks < 4; ++ks) {
            uint32_t a0[4], a1[4];
            ldsm4(a0, wH + aoff0 + ks * 32);
            ldsm4(a1, wH + aoff1 + ks * 32);
#pragma unroll
            for (int n2 = 0; n2 < 4; ++n2) {
                uint32_t bh[4];
                ldsm4t(bh, WhH + boffB + ks * 16 * 272 + n2 * 32);
                mma16816(acc[0][2 * n2],     a0, bh[0], bh[1]);
                mma16816(acc[0][2 * n2 + 1], a0, bh[2], bh[3]);
                mma16816(acc[1][2 * n2],     a1, bh[0], bh[1]);
                mma16816(acc[1][2 * n2 + 1], a1, bh[2], bh[3]);
            }
        }
    };

    // ---- pipeline: wait(c); sync; issue(c+1); score(c); sync; mma(c) ----
    stage_wh(0, 0); stage_adj(0, 0); cpa_commit();
    for (int c = 0; c < 32; ++c) {
        const int p = c & 1;
        asm volatile("cp.async.wait_group 0;");
        __syncthreads();
        if (c + 1 < 32) { stage_wh(c + 1, p ^ 1); stage_adj(c + 1, p ^ 1); cpa_commit(); }
        score(c, p);
        __syncthreads();
        mmaphase(p);
    }

    // ---- l row sums ----
#pragma unroll
    for (int r = 0; r < 16; ++r) {
        float v = warpSum(lsum[r]);
        if (lane == 0) lsh[wrp * 16 + r] = v;
    }

    // ---- per-row partial sums over this warp's d-half ----
    // lane row-slots s: row = iw + s*8 + (lane>>2)  (s = 0..3)
    {
        float S1[4] = {0.f, 0.f, 0.f, 0.f}, S2[4] = {0.f, 0.f, 0.f, 0.f};
#pragma unroll
        for (int ib = 0; ib < 2; ++ib)
#pragma unroll
            for (int nt = 0; nt < 8; ++nt) {
                float a0 = acc[ib][nt][0], a1 = acc[ib][nt][1];
                float a2 = acc[ib][nt][2], a3 = acc[ib][nt][3];
                S1[2 * ib]     += a0 + a1;  S2[2 * ib]     += a0 * a0 + a1 * a1;
                S1[2 * ib + 1] += a2 + a3;  S2[2 * ib + 1] += a2 * a2 + a3 * a3;
            }
#pragma unroll
        for (int s = 0; s < 4; ++s) {
#pragma unroll
            for (int o = 1; o <= 2; o <<= 1) {
                S1[s] += __shfl_xor_sync(0xffffffffu, S1[s], o);
                S2[s] += __shfl_xor_sync(0xffffffffu, S2[s], o);
            }
        }
        if ((lane & 3) == 0) {
            const int dh = wrp >> 1;
#pragma unroll
            for (int s = 0; s < 4; ++s) {
                int row = iw + s * 8 + (lane >> 2);
                red1[row][dh] = S1[s];
                red2[row][dh] = S2[s];
            }
        }
    }
    __syncthreads();

    // ---- combine halves -> mean/rstd per row (rows 0..63 by thread) ----
    if (t < 64) {
        float S1 = red1[t][0] + red1[t][1];
        float S2 = red2[t][0] + red2[t][1];
        float L  = lsh[t];
        float mean = S1 * (1.f / Dd);
        float var  = S2 * (1.f / Dd) - mean * mean;
        mrs[t][0] = mean;
        mrs[t][1] = rsqrtf(var + 1e-5f * L * L);
    }
    __syncthreads();

    // ---- normalize + lrelu + maxpool over this warp's 32 rows ----
    {
        float mean_[4], rstd_[4];
#pragma unroll
        for (int s = 0; s < 4; ++s) {
            int row = iw + s * 8 + (lane >> 2);
            mean_[s] = mrs[row][0];
            rstd_[s] = mrs[row][1];
        }
#pragma unroll
        for (int nt = 0; nt < 8; ++nt) {
            float m0 = -3.402823466e38f, m1 = m0;
#pragma unroll
            for (int ib = 0; ib < 2; ++ib) {
                int slo = 2 * ib, shi = 2 * ib + 1;
                m0 = fmaxf(m0, lrelu((acc[ib][nt][0] - mean_[slo]) * rstd_[slo]));
                m1 = fmaxf(m1, lrelu((acc[ib][nt][1] - mean_[slo]) * rstd_[slo]));
                m0 = fmaxf(m0, lrelu((acc[ib][nt][2] - mean_[shi]) * rstd_[shi]));
                m1 = fmaxf(m1, lrelu((acc[ib][nt][3] - mean_[shi]) * rstd_[shi]));
            }
#pragma unroll
            for (int o = 4; o <= 16; o <<= 1) {
                m0 = fmaxf(m0, __shfl_xor_sync(0xffffffffu, m0, o));
                m1 = fmaxf(m1, __shfl_xor_sync(0xffffffffu, m1, o));
            }
            if (lane < 4) {
                pm[wrp][nt * 8 + (lane & 3) * 2]     = m0;
                pm[wrp][nt * 8 + (lane & 3) * 2 + 1] = m1;
            }
        }
    }
    __syncthreads();
    if (t < 128) {
        float mx = (t < 64) ? fmaxf(pm[0][t], pm[1][t])
                            : fmaxf(pm[2][t - 64], pm[3][t - 64]);
        atomicMaxFloat(&g_pooled[(b << 7) + t], mx);
    }
}

// ---------------- K3: head + log_softmax ----------------
__global__ void k3_out(const float* __restrict__ W2, const float* __restrict__ b2,
                       float* __restrict__ out)
{
    const int t = threadIdx.x, b = t >> 5, lane = t & 31;
    if (b < Bb) {
        float p0 = 0.f, p1 = 0.f;
        for (int d = lane; d < Dd; d += 32) {
            float pv = g_pooled[b * Dd + d];
            p0 += pv * W2[d];
            p1 += pv * W2[Dd + d];
        }
        p0 = warpSum(p0);
        p1 = warpSum(p1);
        if (lane == 0) {
            float o0 = p0 + b2[0], o1 = p1 + b2[1];
            float m = fmaxf(o0, o1);
            float lse = m + logf(expf(o0 - m) + expf(o1 - m));
            out[b * 2 + 0] = o0 - lse;
            out[b * 2 + 1] = o1 - lse;
        }
    }
}

// ---------------- launch ----------------
extern "C" void kernel_launch(void* const* d_in, const int* in_sizes, int n_in,
                              void* d_out, int out_size)
{
    const float* h   = (const float*)d_in[0];
    const int*   adj = (const int*)  d_in[1];
    const float* W1  = (const float*)d_in[2];
    const float* b1  = (const float*)d_in[3];
    const float* Wg  = (const float*)d_in[4];
    const float* bg  = (const float*)d_in[5];
    const float* a1  = (const float*)d_in[6];
    const float* a2  = (const float*)d_in[7];
    const float* W2  = (const float*)d_in[8];
    const float* b2  = (const float*)d_in[9];
    float* out = (float*)d_out;

    const int smem_k1 = 148480;
    const int smem_k2 = 76800;
    cudaFuncSetAttribute(k1, cudaFuncAttributeMaxDynamicSharedMemorySize, smem_k1);
    cudaFuncSetAttribute(k2_attn, cudaFuncAttributeMaxDynamicSharedMemorySize, smem_k2);

    k1<<<128, 512, smem_k1>>>(h, W1, b1, Wg, bg, a1, a2);
    k1c<<<8, 1024>>>();
    k2_attn<<<256, 128, smem_k2>>>(adj);
    k3_out<<<1, 256>>>(W2, b2, out);
}

// round 16
// speedup vs baseline: 6.3527x; 1.0758x over previous
#include <cuda_runtime.h>
#include <cuda_fp16.h>
#include <cstdint>

#define Bb 8
#define Nn 2048
#define Dd 128
#define Fin 10
#define ALPHA 0.02f
typedef unsigned long long ull;

// ---------------- device scratch ----------------
__device__ __align__(16) __half g_Whh[Bb * Nn * Dd];   // 4MB fp16 Wh
__device__ float g_e1[Bb * Nn];
__device__ float g_e2[Bb * Nn];
__device__ float g_P[Bb * Nn];
__device__ float g_R[Bb * Nn];
__device__ __align__(16) float4 g_QS[Bb * Nn];         // (e2, Q, S, 0)
__device__ float g_e2max[Bb] = {-3.402823466e38f, -3.402823466e38f, -3.402823466e38f,
                                -3.402823466e38f, -3.402823466e38f, -3.402823466e38f,
                                -3.402823466e38f, -3.402823466e38f};
__device__ float g_pooled[Bb * Dd];
__device__ int g_ctrB[Bb];      // cumulative; mask &15
__device__ int g_ctr2;          // cumulative; mask &255

// ---------------- helpers ----------------
__device__ __forceinline__ float warpSum(float v) {
#pragma unroll
    for (int o = 16; o > 0; o >>= 1) v += __shfl_xor_sync(0xffffffffu, v, o);
    return v;
}
__device__ __forceinline__ float lrelu(float x) { return fmaxf(x, ALPHA * x); }
__device__ __forceinline__ void atomicMaxFloat(float* a, float v) {
    if (v >= 0.f) atomicMax((int*)a, __float_as_int(v));
    else          atomicMin((unsigned int*)a, __float_as_uint(v));
}
__device__ __forceinline__ void ffma2(ull& a, ull b, ull c) {
    asm("fma.rn.f32x2 %0, %1, %2, %0;" : "+l"(a) : "l"(b), "l"(c));
}
__device__ __forceinline__ ull packf2(float v) {
    ull r; asm("mov.b64 %0, {%1, %1};" : "=l"(r) : "f"(v)); return r;
}
__device__ __forceinline__ uint32_t smem_u32(const void* p) {
    uint32_t a;
    asm("{ .reg .u64 t; cvta.to.shared.u64 t, %1; cvt.u32.u64 %0, t; }" : "=r"(a) : "l"(p));
    return a;
}
__device__ __forceinline__ void ldsm4(uint32_t* r, uint32_t a) {
    asm volatile("ldmatrix.sync.aligned.m8n8.x4.shared.b16 {%0,%1,%2,%3}, [%4];"
        : "=r"(r[0]), "=r"(r[1]), "=r"(r[2]), "=r"(r[3]) : "r"(a));
}
__device__ __forceinline__ void ldsm4t(uint32_t* r, uint32_t a) {
    asm volatile("ldmatrix.sync.aligned.m8n8.x4.trans.shared.b16 {%0,%1,%2,%3}, [%4];"
        : "=r"(r[0]), "=r"(r[1]), "=r"(r[2]), "=r"(r[3]) : "r"(a));
}
__device__ __forceinline__ void mma16816(float* d, const uint32_t* a, uint32_t b0, uint32_t b1) {
    asm volatile("mma.sync.aligned.m16n8k16.row.col.f32.f16.f16.f32 "
        "{%0,%1,%2,%3},{%4,%5,%6,%7},{%8,%9},{%0,%1,%2,%3};"
        : "+f"(d[0]), "+f"(d[1]), "+f"(d[2]), "+f"(d[3])
        : "r"(a[0]), "r"(a[1]), "r"(a[2]), "r"(a[3]), "r"(b0), "r"(b1));
}
__device__ __forceinline__ void cpa16(uint32_t dst, const void* src) {
    asm volatile("cp.async.cg.shared.global [%0], [%1], 16;" :: "r"(dst), "l"(src));
}
__device__ __forceinline__ void cpa_commit() { asm volatile("cp.async.commit_group;"); }
#define BARS(id, cnt) asm volatile("bar.sync %0, %1;" :: "r"(id), "r"(cnt) : "memory")
#define BARA(id, cnt) asm volatile("bar.arrive %0, %1;" :: "r"(id), "r"(cnt) : "memory")

// ---------------- K1: fc1+LN+lrelu -> Wg GEMM -> e1/e2 -> Wh fp16 (+fused k1c tail) ---
// 128 blocks x 512 threads; block = 128 nodes
__global__ __launch_bounds__(512, 1) void k1(
    const float* __restrict__ h, const float* __restrict__ W1, const float* __restrict__ b1,
    const float* __restrict__ Wg, const float* __restrict__ bg,
    const float* __restrict__ a1, const float* __restrict__ a2)
{
    extern __shared__ __align__(16) float sm[];
    float* wgt = sm;                 // [128 k][132]
    float* xsh = sm + 16896;         // [128 n][129]
    float* hsh = sm + 33408;         // [128 n][10]
    float* w1s = sm + 34688;         // [128 d][10]
    float* b1s = sm + 35968;         // [128]
    float* red = sm + 36096;         // [2][4][128]
    __shared__ int slast;

    const int t = threadIdx.x, lane = t & 31, wrp = t >> 5;
    const int n0 = blockIdx.x * 128;
    const int b  = blockIdx.x >> 4;

#pragma unroll
    for (int it = 0; it < 32; ++it) {
        int idx = it * 512 + t;
        wgt[(idx & 127) * 132 + (idx >> 7)] = Wg[idx];
    }
#pragma unroll
    for (int idx = t; idx < 128 * Fin; idx += 512) {
        hsh[idx] = h[n0 * Fin + idx];
        w1s[idx] = W1[idx];
    }
    if (t < 128) b1s[t] = b1[t];
    __syncthreads();

    {
        const int n = t & 127, qq = t >> 7;
        float hv[Fin];
#pragma unroll
        for (int f = 0; f < Fin; ++f) hv[f] = hsh[n * Fin + f];
        float xr[32], s1 = 0.f, s2 = 0.f;
#pragma unroll
        for (int k = 0; k < 32; ++k) {
            const int d = qq * 32 + k;
            float x = b1s[d];
#pragma unroll
            for (int f = 0; f < Fin; ++f) x += hv[f] * w1s[d * Fin + f];
            xr[k] = x; s1 += x; s2 += x * x;
        }
        red[qq * 128 + n] = s1;
        red[512 + qq * 128 + n] = s2;
        __syncthreads();
        float S1 = red[n] + red[128 + n] + red[256 + n] + red[384 + n];
        float S2 = red[512 + n] + red[640 + n] + red[768 + n] + red[896 + n];
        float mean = S1 * (1.f / Dd);
        float var  = S2 * (1.f / Dd) - mean * mean;
        float rstd = rsqrtf(var + 1e-5f);
#pragma unroll
        for (int k = 0; k < 32; ++k)
            xsh[n * 129 + qq * 32 + k] = lrelu((xr[k] - mean) * rstd);
    }
    __syncthreads();

    ull acc[8][2];
#pragma unroll
    for (int n = 0; n < 8; ++n) { acc[n][0] = 0ull; acc[n][1] = 0ull; }
    for (int k = 0; k < 128; ++k) {
        ulonglong2 wv = *(const ulonglong2*)&wgt[k * 132 + lane * 4];
#pragma unroll
        for (int n = 0; n < 8; ++n) {
            ull xx = packf2(xsh[(wrp * 8 + n) * 129 + k]);
            ffma2(acc[n][0], xx, wv.x);
            ffma2(acc[n][1], xx, wv.y);
        }
    }

    const float4 bgv = ((const float4*)bg)[lane];
    const float4 a1v = ((const float4*)a1)[lane];
    const float4 a2v = ((const float4*)a2)[lane];
    float e2mx = -3.402823466e38f;
#pragma unroll
    for (int n = 0; n < 8; ++n) {
        const int node = n0 + wrp * 8 + n;
        float2 lo = *(float2*)&acc[n][0];
        float2 hi = *(float2*)&acc[n][1];
        float v0 = lo.x + bgv.x, v1 = lo.y + bgv.y;
        float v2 = hi.x + bgv.z, v3 = hi.y + bgv.w;

        ((__half2*)g_Whh)[node * 64 + lane * 2]     = __floats2half2_rn(v0, v1);
        ((__half2*)g_Whh)[node * 64 + lane * 2 + 1] = __floats2half2_rn(v2, v3);

        float p1 = warpSum(v0 * a1v.x + v1 * a1v.y + v2 * a1v.z + v3 * a1v.w);
        float p2 = warpSum(v0 * a2v.x + v1 * a2v.y + v2 * a2v.z + v3 * a2v.w);
        if (lane == 0) {
            g_e1[node] = p1;
            g_e2[node] = p2;
            e2mx = fmaxf(e2mx, p2);
        }
    }
    if (lane == 0) atomicMaxFloat(&g_e2max[b], e2mx);

    // ---- fused k1c: last block of this batch computes P/R/QS + pooled init ----
    __threadfence();
    if (t == 0) slast = ((atomicAdd(&g_ctrB[b], 1) & 15) == 15);
    __syncthreads();
    if (slast) {
        __threadfence();
        float em = g_e2max[b];
        if (t < 128) g_pooled[b * 128 + t] = -3.402823466e38f;
#pragma unroll
        for (int k = 0; k < 4; ++k) {
            int idx = (b << 11) + k * 512 + t;
            float e1 = g_e1[idx], e2 = g_e2[idx];
            float m = lrelu(e1 + em);
            g_P[idx] = __expf(e1 + em - m);
            g_R[idx] = __expf(ALPHA * (e1 + em) - m);
            g_QS[idx] = make_float4(e2, __expf(e2 - em), __expf(ALPHA * (e2 - em)), 0.f);
        }
    }
}

// ---------------- K2: warp-specialized attention (+fused k3 tail) ----------------
// 256 blocks x 256 threads; block = (b, 64 i-rows); 32 chunks of 64 j.
// Warps 0-3: MMA (+Wh cp.async). Warps 4-7: score (+adj cp.async, warp-private rows).
// smem dyn: WhH[2] @ 0/17408 (64r x 272B); adj[2] @ 34816/51200 (64r x 256B);
//           w[2] @ 67584/76800 (64r x 144B). Total 86016 B.
// Named barriers: B0=1,B1=2 (w ready), A0=3,A1=4 (w free), 5 = mma-internal, 6 = joint.
__global__ __launch_bounds__(256, 2) void k2_attn(const int* __restrict__ adj,
    const float* __restrict__ W2, const float* __restrict__ b2, float* __restrict__ out)
{
    extern __shared__ __align__(16) char smd[];
    __shared__ float e1s[64], Ps[64], Rs[64], lsh[64];
    __shared__ float red1[64][2], red2[64][2], mrs[64][2];
    __shared__ float pm[4][64];
    __shared__ int slast;

    const int t = threadIdx.x, lane = t & 31, wrp = t >> 5;
    const int b  = blockIdx.x >> 5;
    const int i0 = (blockIdx.x & 31) << 6;
    const uint32_t base = smem_u32(smd);

    if (t < 64) {
        int idx = (b << 11) + i0 + t;
        e1s[t] = g_e1[idx];
        Ps[t]  = g_P[idx];
        Rs[t]  = g_R[idx];
    }
    __syncthreads();

    if (wrp < 4) {
        // ================= MMA warps =================
        float acc[2][8][4];
#pragma unroll
        for (int ib = 0; ib < 2; ++ib)
#pragma unroll
            for (int nt = 0; nt < 8; ++nt)
#pragma unroll
                for (int q = 0; q < 4; ++q) acc[ib][nt][q] = 0.f;

        auto stage_wh = [&](int cc, int bf) {
            const char* sH = (const char*)(g_Whh + ((size_t)((b << 11) + cc * 64) << 7));
            uint32_t dH = base + bf * 17408;
#pragma unroll
            for (int q = 0; q < 8; ++q) {
                int task = q * 128 + t;
                int row = task >> 4, seg = task & 15;
                cpa16(dH + row * 272 + seg * 16, sH + row * 256 + seg * 16);
            }
        };
        const int iw = (wrp & 1) * 32;
        const int dw = (wrp >> 1) * 64;
        const uint32_t lrr  = ((lane >> 3) & 1) * 8 + (lane & 7);
        const uint32_t csel = (lane >> 4) * 16;

        stage_wh(0, 0); cpa_commit();
        for (int c = 0; c < 32; ++c) {
            const int p = c & 1;
            if (c < 31) { stage_wh(c + 1, p ^ 1); cpa_commit(); }
            if (c < 31) asm volatile("cp.async.wait_group 1;");
            else        asm volatile("cp.async.wait_group 0;");
            BARS(5, 128);                  // Wh(c) fully staged across mma warps
            BARS(1 + p, 256);              // w(c) ready
            {
                uint32_t wH  = base + 67584 + p * 9216;
                uint32_t WhH = base + p * 17408;
                const uint32_t aoff0 = (iw + lrr) * 144 + csel;
                const uint32_t aoff1 = (iw + 16 + lrr) * 144 + csel;
                const uint32_t boffB = lrr * 272 + csel + dw * 2;
#pragma unroll
                for (int ks = 0; ks < 4; ++ks) {
                    uint32_t a0[4], a1[4];
                    ldsm4(a0, wH + aoff0 + ks * 32);
                    ldsm4(a1, wH + aoff1 + ks * 32);
#pragma unroll
                    for (int n2 = 0; n2 < 4; ++n2) {
                        uint32_t bh[4];
                        ldsm4t(bh, WhH + boffB + ks * 16 * 272 + n2 * 32);
                        mma16816(acc[0][2 * n2],     a0, bh[0], bh[1]);
                        mma16816(acc[0][2 * n2 + 1], a0, bh[2], bh[3]);
                        mma16816(acc[1][2 * n2],     a1, bh[0], bh[1]);
                        mma16816(acc[1][2 * n2 + 1], a1, bh[2], bh[3]);
                    }
                }
            }
            BARA(3 + p, 256);              // w buffer p free
        }

        // per-row partials over this warp's d-half
        {
            float S1[4] = {0.f, 0.f, 0.f, 0.f}, S2[4] = {0.f, 0.f, 0.f, 0.f};
#pragma unroll
            for (int ib = 0; ib < 2; ++ib)
#pragma unroll
                for (int nt = 0; nt < 8; ++nt) {
                    float a0 = acc[ib][nt][0], a1 = acc[ib][nt][1];
                    float a2 = acc[ib][nt][2], a3 = acc[ib][nt][3];
                    S1[2 * ib]     += a0 + a1;  S2[2 * ib]     += a0 * a0 + a1 * a1;
                    S1[2 * ib + 1] += a2 + a3;  S2[2 * ib + 1] += a2 * a2 + a3 * a3;
                }
#pragma unroll
            for (int s = 0; s < 4; ++s)
#pragma unroll
                for (int o = 1; o <= 2; o <<= 1) {
                    S1[s] += __shfl_xor_sync(0xffffffffu, S1[s], o);
                    S2[s] += __shfl_xor_sync(0xffffffffu, S2[s], o);
                }
            if ((lane & 3) == 0) {
                const int dh = wrp >> 1;
#pragma unroll
                for (int s = 0; s < 4; ++s) {
                    int row = iw + s * 8 + (lane >> 2);
                    red1[row][dh] = S1[s];
                    red2[row][dh] = S2[s];
                }
            }
        }
        BARS(6, 256);                      // join: lsh (score) + red (mma) visible

        if (t < 64) {
            float S1 = red1[t][0] + red1[t][1];
            float S2 = red2[t][0] + red2[t][1];
            float L  = lsh[t];
            float mean = S1 * (1.f / Dd);
            float var  = S2 * (1.f / Dd) - mean * mean;
            mrs[t][0] = mean;
            mrs[t][1] = rsqrtf(var + 1e-5f * L * L);
        }
        BARS(5, 128);

        {
            float mean_[4], rstd_[4];
#pragma unroll
            for (int s = 0; s < 4; ++s) {
                int row = iw + s * 8 + (lane >> 2);
                mean_[s] = mrs[row][0];
                rstd_[s] = mrs[row][1];
            }
#pragma unroll
            for (int nt = 0; nt < 8; ++nt) {
                float m0 = -3.402823466e38f, m1 = m0;
#pragma unroll
                for (int ib = 0; ib < 2; ++ib) {
                    int slo = 2 * ib, shi = 2 * ib + 1;
                    m0 = fmaxf(m0, lrelu((acc[ib][nt][0] - mean_[slo]) * rstd_[slo]));
                    m1 = fmaxf(m1, lrelu((acc[ib][nt][1] - mean_[slo]) * rstd_[slo]));
                    m0 = fmaxf(m0, lrelu((acc[ib][nt][2] - mean_[shi]) * rstd_[shi]));
                    m1 = fmaxf(m1, lrelu((acc[ib][nt][3] - mean_[shi]) * rstd_[shi]));
                }
#pragma unroll
                for (int o = 4; o <= 16; o <<= 1) {
                    m0 = fmaxf(m0, __shfl_xor_sync(0xffffffffu, m0, o));
                    m1 = fmaxf(m1, __shfl_xor_sync(0xffffffffu, m1, o));
                }
                if (lane < 4) {
                    pm[wrp][nt * 8 + (lane & 3) * 2]     = m0;
                    pm[wrp][nt * 8 + (lane & 3) * 2 + 1] = m1;
                }
            }
        }
        BARS(5, 128);
        {
            float mx = (t < 64) ? fmaxf(pm[0][t], pm[1][t])
                                : fmaxf(pm[2][t - 64], pm[3][t - 64]);
            atomicMaxFloat(&g_pooled[(b << 7) + ((wrp >> 1) ? 64 : 0) + (t & 63)], mx);
        }
    } else {
        // ================= score warps =================
        const int sw = wrp - 4;
        float lsum[16];
#pragma unroll
        for (int r = 0; r < 16; ++r) lsum[r] = 0.f;

        auto stage_adj = [&](int cc, int bf) {
            const char* sA = (const char*)(adj + ((size_t)((b << 11) + i0) << 11) + cc * 64);
            uint32_t dA = base + 34816 + bf * 16384;
#pragma unroll
            for (int q = 0; q < 8; ++q) {
                int task = q * 32 + lane;
                int row = sw * 16 + (task >> 4), seg = task & 15;
                cpa16(dA + row * 256 + seg * 16, sA + (size_t)row * 8192 + seg * 16);
            }
        };

        stage_adj(0, 0); cpa_commit();
        for (int c = 0; c < 32; ++c) {
            const int p = c & 1;
            if (c < 31) { stage_adj(c + 1, p ^ 1); cpa_commit(); }
            if (c < 31) asm volatile("cp.async.wait_group 1;");
            else        asm volatile("cp.async.wait_group 0;");
            __syncwarp();
            if (c >= 2) BARS(3 + p, 256);   // w buffer p free
            {
                const uint32_t aOff = 34816 + p * 16384;
                const uint32_t wOff = 67584 + p * 9216;
                const float4 qs0 = g_QS[(b << 11) + c * 64 + 2 * lane];
                const float4 qs1 = g_QS[(b << 11) + c * 64 + 2 * lane + 1];
                const int rbase = sw * 16;
#pragma unroll
                for (int r = 0; r < 16; ++r) {
                    const int row = rbase + r;
                    int2 av = *(const int2*)(smd + aOff + row * 256 + lane * 8);
                    float e1r = e1s[row], Pr = Ps[row], Rr = Rs[row];
                    float f0 = (e1r + qs0.x >= 0.f) ? Pr * qs0.y : Rr * qs0.z;
                    float f1 = (e1r + qs1.x >= 0.f) ? Pr * qs1.y : Rr * qs1.z;
                    float w0 = (av.x != 0) ? f0 : 0.f;
                    float w1 = (av.y != 0) ? f1 : 0.f;
                    lsum[r] += w0 + w1;
                    *(__half2*)(smd + wOff + row * 144 + lane * 4) = __floats2half2_rn(w0, w1);
                }
            }
            BARA(1 + p, 256);               // w(c) ready
        }
#pragma unroll
        for (int r = 0; r < 16; ++r) {
            float v = warpSum(lsum[r]);
            if (lane == 0) lsh[sw * 16 + r] = v;
        }
        BARS(6, 256);                       // join
    }

    // ---- fused k3: last block computes head + log_softmax ----
    __syncthreads();
    __threadfence();
    if (t == 0) slast = ((atomicAdd(&g_ctr2, 1) & 255) == 255);
    __syncthreads();
    if (slast) {
        __threadfence();
        const int bo = t >> 5, ln = t & 31;
        float p0 = 0.f, p1 = 0.f;
        for (int d = ln; d < Dd; d += 32) {
            float pv = g_pooled[bo * Dd + d];
            p0 += pv * W2[d];
            p1 += pv * W2[Dd + d];
        }
        p0 = warpSum(p0);
        p1 = warpSum(p1);
        if (ln == 0) {
            float o0 = p0 + b2[0], o1 = p1 + b2[1];
            float m = fmaxf(o0, o1);
            float lse = m + logf(expf(o0 - m) + expf(o1 - m));
            out[bo * 2 + 0] = o0 - lse;
            out[bo * 2 + 1] = o1 - lse;
        }
    }
}

// ---------------- launch ----------------
extern "C" void kernel_launch(void* const* d_in, const int* in_sizes, int n_in,
                              void* d_out, int out_size)
{
    const float* h   = (const float*)d_in[0];
    const int*   adj = (const int*)  d_in[1];
    const float* W1  = (const float*)d_in[2];
    const float* b1  = (const float*)d_in[3];
    const float* Wg  = (const float*)d_in[4];
    const float* bg  = (const float*)d_in[5];
    const float* a1  = (const float*)d_in[6];
    const float* a2  = (const float*)d_in[7];
    const float* W2  = (const float*)d_in[8];
    const float* b2  = (const float*)d_in[9];
    float* out = (float*)d_out;

    const int smem_k1 = 148480;
    const int smem_k2 = 86016;
    cudaFuncSetAttribute(k1, cudaFuncAttributeMaxDynamicSharedMemorySize, smem_k1);
    cudaFuncSetAttribute(k2_attn, cudaFuncAttributeMaxDynamicSharedMemorySize, smem_k2);

    k1<<<128, 512, smem_k1>>>(h, W1, b1, Wg, bg, a1, a2);
    k2_attn<<<256, 256, smem_k2>>>(adj, W2, b2, out);
}